// round 8
// baseline (speedup 1.0000x reference)
#include <cuda_runtime.h>
#include <cuda_bf16.h>
#include <stdint.h>
#include <math.h>

// ---------------------------------------------------------------------------
// Problem constants
// ---------------------------------------------------------------------------
#define N_EMBD 2048
#define NH     16
#define HD     128
#define TT     2048         // seq len
#define BB     2            // batch
#define MROWS  (BB * TT)    // 4096 flattened (b, t) rows
#define QKV_N  (3 * N_EMBD) // 6144

// ---------------------------------------------------------------------------
// Scratch (no cudaMalloc allowed -> static __device__ globals)
// ---------------------------------------------------------------------------
__device__ float g_qkv[(size_t)MROWS * QKV_N];   // 100.7 MB
__device__ float g_y[(size_t)MROWS * N_EMBD];    //  33.6 MB
__device__ float g_cos[TT * (HD / 2)];
__device__ float g_sin[TT * (HD / 2)];
// bf16 hi/lo split operands (multi-purpose, reused across phases)
__device__ __nv_bfloat16 g_Ah[(size_t)MROWS * N_EMBD];   // x-split / q-split / y-split
__device__ __nv_bfloat16 g_Al[(size_t)MROWS * N_EMBD];
__device__ __nv_bfloat16 g_Bh[(size_t)QKV_N * N_EMBD];   // w_attn^T / k-split / w_proj^T
__device__ __nv_bfloat16 g_Bl[(size_t)QKV_N * N_EMBD];
__device__ __nv_bfloat16 g_Vth[(size_t)MROWS * N_EMBD];  // V^T per head [bh][d][t]
__device__ __nv_bfloat16 g_Vtl[(size_t)MROWS * N_EMBD];

// ---------------------------------------------------------------------------
// Helpers (plain sm_103-legal PTX only: ldmatrix / mma.sync / cp.async)
// ---------------------------------------------------------------------------
__device__ __forceinline__ uint32_t smem_u32(const void* p) {
    uint32_t a;
    asm("{ .reg .u64 t; cvta.to.shared.u64 t, %1; cvt.u32.u64 %0, t; }"
        : "=r"(a) : "l"(p));
    return a;
}

__device__ __forceinline__ void ldsm_x4(uint32_t* r, uint32_t addr) {
    asm volatile("ldmatrix.sync.aligned.m8n8.x4.shared.b16 {%0,%1,%2,%3}, [%4];"
                 : "=r"(r[0]), "=r"(r[1]), "=r"(r[2]), "=r"(r[3]) : "r"(addr));
}

__device__ __forceinline__ void mma16816(float* c, const uint32_t* a,
                                         const uint32_t* b) {
    asm volatile(
        "mma.sync.aligned.m16n8k16.row.col.f32.bf16.bf16.f32 "
        "{%0,%1,%2,%3}, {%4,%5,%6,%7}, {%8,%9}, {%0,%1,%2,%3};"
        : "+f"(c[0]), "+f"(c[1]), "+f"(c[2]), "+f"(c[3])
        : "r"(a[0]), "r"(a[1]), "r"(a[2]), "r"(a[3]), "r"(b[0]), "r"(b[1]));
}

#define CP_ASYNC16(dst, src) \
    asm volatile("cp.async.cg.shared.global [%0], [%1], 16;" \
                 :: "r"(dst), "l"(src) : "memory")
#define CP_COMMIT() asm volatile("cp.async.commit_group;" ::: "memory")
#define CP_WAIT1()  asm volatile("cp.async.wait_group 1;" ::: "memory")

__device__ __forceinline__ void split2(float x, __nv_bfloat16& h, __nv_bfloat16& l) {
    h = __float2bfloat16(x);
    l = __float2bfloat16(x - __bfloat162float(h));
}

// pack two floats into bf16x2 hi + residual bf16x2 lo
__device__ __forceinline__ void pack_hl(float x, float y, uint32_t& h, uint32_t& l) {
    __nv_bfloat162 hh = __floats2bfloat162_rn(x, y);
    float rx = x - __bfloat162float(hh.x);
    float ry = y - __bfloat162float(hh.y);
    __nv_bfloat162 ll = __floats2bfloat162_rn(rx, ry);
    h = *(uint32_t*)&hh;
    l = *(uint32_t*)&ll;
}

// ---------------------------------------------------------------------------
// Convert kernels
// ---------------------------------------------------------------------------
__global__ void conv_rm_kernel(const float* __restrict__ in,
                               __nv_bfloat16* __restrict__ oh,
                               __nv_bfloat16* __restrict__ ol, int n4) {
    int idx = blockIdx.x * blockDim.x + threadIdx.x;
    if (idx >= n4) return;
    float4 v = ((const float4*)in)[idx];
    __nv_bfloat16 h0, h1, h2, h3, l0, l1, l2, l3;
    split2(v.x, h0, l0); split2(v.y, h1, l1);
    split2(v.z, h2, l2); split2(v.w, h3, l3);
    ((__nv_bfloat162*)oh)[idx * 2]     = __halves2bfloat162(h0, h1);
    ((__nv_bfloat162*)oh)[idx * 2 + 1] = __halves2bfloat162(h2, h3);
    ((__nv_bfloat162*)ol)[idx * 2]     = __halves2bfloat162(l0, l1);
    ((__nv_bfloat162*)ol)[idx * 2 + 1] = __halves2bfloat162(l2, l3);
}

// B[K][N] fp32 row-major -> BT[N][K] bf16 hi/lo
__global__ void conv_tr_kernel(const float* __restrict__ B,
                               __nv_bfloat16* __restrict__ bh,
                               __nv_bfloat16* __restrict__ bl, int K, int N) {
    __shared__ float tile[32][33];
    int n0 = blockIdx.x * 32, k0 = blockIdx.y * 32;
    int tx = threadIdx.x, ty = threadIdx.y;
#pragma unroll
    for (int i = 0; i < 4; i++)
        tile[ty + i * 8][tx] = B[(size_t)(k0 + ty + i * 8) * N + n0 + tx];
    __syncthreads();
#pragma unroll
    for (int i = 0; i < 4; i++) {
        int n = ty + i * 8;
        float v = tile[tx][n];
        __nv_bfloat16 h, l;
        split2(v, h, l);
        size_t o = (size_t)(n0 + n) * K + k0 + tx;
        bh[o] = h;
        bl[o] = l;
    }
}

// q or k section of g_qkv: apply RoPE + split to bf16 hi/lo [m][2048]
__global__ void conv_rope_kernel(const float* __restrict__ qkv, int secOff,
                                 __nv_bfloat16* __restrict__ oh,
                                 __nv_bfloat16* __restrict__ ol) {
    int idx = blockIdx.x * blockDim.x + threadIdx.x;
    if (idx >= MROWS * 512) return;
    int m = idx >> 9;
    int col = (idx & 511) * 4;
    int t = m & (TT - 1);
    int i0 = (col & 127) >> 1;
    float4 v = *(const float4*)(qkv + (size_t)m * QKV_N + secOff + col);
    float c0 = g_cos[t * 64 + i0],     s0 = g_sin[t * 64 + i0];
    float c1 = g_cos[t * 64 + i0 + 1], s1 = g_sin[t * 64 + i0 + 1];
    float r0 = v.x * c0 - v.y * s0;
    float r1 = v.y * c0 + v.x * s0;
    float r2 = v.z * c1 - v.w * s1;
    float r3 = v.w * c1 + v.z * s1;
    __nv_bfloat16 h0, h1, h2, h3, l0, l1, l2, l3;
    split2(r0, h0, l0); split2(r1, h1, l1);
    split2(r2, h2, l2); split2(r3, h3, l3);
    size_t o = (size_t)m * N_EMBD + col;
    *(__nv_bfloat162*)(oh + o)     = __halves2bfloat162(h0, h1);
    *(__nv_bfloat162*)(oh + o + 2) = __halves2bfloat162(h2, h3);
    *(__nv_bfloat162*)(ol + o)     = __halves2bfloat162(l0, l1);
    *(__nv_bfloat162*)(ol + o + 2) = __halves2bfloat162(l2, l3);
}

// V section of g_qkv -> per-head transposed bf16 hi/lo: vt[(bh*128+d)*2048 + t]
__global__ void conv_vt_kernel(const float* __restrict__ qkv,
                               __nv_bfloat16* __restrict__ vh,
                               __nv_bfloat16* __restrict__ vl) {
    __shared__ float tile[32][33];
    int bh = blockIdx.z;
    int b = bh >> 4, h = bh & 15;
    int t0 = blockIdx.x * 32, d0 = blockIdx.y * 32;
    int tx = threadIdx.x, ty = threadIdx.y;
#pragma unroll
    for (int i = 0; i < 4; i++)
        tile[ty + i * 8][tx] =
            qkv[(size_t)(b * TT + t0 + ty + i * 8) * QKV_N + 2 * N_EMBD + h * HD + d0 + tx];
    __syncthreads();
#pragma unroll
    for (int i = 0; i < 4; i++) {
        int d = ty + i * 8;
        float v = tile[tx][d];
        __nv_bfloat16 hh, ll;
        split2(v, hh, ll);
        size_t o = (size_t)(bh * HD + d0 + d) * TT + t0 + tx;
        vh[o] = hh;
        vl[o] = ll;
    }
}

// ---------------------------------------------------------------------------
// RoPE table
// ---------------------------------------------------------------------------
__global__ void rope_table_kernel() {
    int idx = blockIdx.x * blockDim.x + threadIdx.x;
    if (idx >= TT * 64) return;
    int t = idx >> 6;
    int i = idx & 63;
    double theta = pow(10000.0, -(double)i / 64.0);
    double ang = (double)t * theta;
    g_cos[idx] = (float)cos(ang);
    g_sin[idx] = (float)sin(ang);
}

// ---------------------------------------------------------------------------
// Tensor-core GEMM via mma.sync. CTA tile 128x256, BK=32, 8 warps, each
// warp computes 64x64. MMA issue order is TERM-MAJOR so same-accumulator
// reuse distance is 8 (hides HMMA RAW latency).
// ---------------------------------------------------------------------------
#define BM 128
#define BN 256
#define BK 32
#define PADB 80
#define A_BYTES (128 * PADB)
#define B_BYTES (256 * PADB)
#define STG_BYTES (2 * A_BYTES + 2 * B_BYTES)   // 61440
#define GEMM_SMEM (2 * STG_BYTES)               // 122880

__global__ __launch_bounds__(256, 1) void gemm_mma_kernel(
    const __nv_bfloat16* __restrict__ Ah, const __nv_bfloat16* __restrict__ Al,
    const __nv_bfloat16* __restrict__ Bh, const __nv_bfloat16* __restrict__ Bl,
    float* __restrict__ C, int M, int N, int K)
{
    extern __shared__ char smc[];
    const uint32_t sbase = smem_u32(smc);
    const int tid = threadIdx.x;
    const int lane = tid & 31;
    const int wid = tid >> 5;
    const int wm = wid & 1;
    const int wn = wid >> 1;
    const int mBase = blockIdx.y * BM;
    const int nBase = blockIdx.x * BN;
    const int nch = K / BK;

    const int ldRow = tid >> 2;
    const int ldCh  = tid & 3;

    float acc[4][8][4];
#pragma unroll
    for (int i = 0; i < 4; i++)
#pragma unroll
        for (int j = 0; j < 8; j++)
#pragma unroll
            for (int r = 0; r < 4; r++) acc[i][j][r] = 0.0f;

    auto issue_stage = [&](int c, int buf) {
        const uint32_t st = sbase + buf * STG_BYTES;
        const int kOff = c * BK;
#pragma unroll
        for (int i = 0; i < 2; i++) {
            const int row = i * 64 + ldRow;
            const uint32_t so = row * PADB + ldCh * 16;
            CP_ASYNC16(st + so,
                       Ah + (size_t)(mBase + row) * K + kOff + ldCh * 8);
            CP_ASYNC16(st + A_BYTES + so,
                       Al + (size_t)(mBase + row) * K + kOff + ldCh * 8);
        }
#pragma unroll
        for (int i = 0; i < 4; i++) {
            const int row = i * 64 + ldRow;
            const uint32_t so = row * PADB + ldCh * 16;
            CP_ASYNC16(st + 2 * A_BYTES + so,
                       Bh + (size_t)(nBase + row) * K + kOff + ldCh * 8);
            CP_ASYNC16(st + 2 * A_BYTES + B_BYTES + so,
                       Bl + (size_t)(nBase + row) * K + kOff + ldCh * 8);
        }
    };

    issue_stage(0, 0);
    CP_COMMIT();

    const int arow = (lane & 7) + ((lane >> 3) & 1) * 8;
    const int akc8 = (lane >> 4) * 8;
    const int brow = (lane & 7) + ((lane >> 4) & 1) * 8;
    const int bkc8 = ((lane >> 3) & 1) * 8;

    for (int c = 0; c < nch; c++) {
        const int buf = c & 1;
        if (c + 1 < nch) issue_stage(c + 1, (c + 1) & 1);
        CP_COMMIT();
        CP_WAIT1();
        __syncthreads();

        const uint32_t st = sbase + buf * STG_BYTES;
        const uint32_t ahB = st;
        const uint32_t alB = st + A_BYTES;
        const uint32_t bhB = st + 2 * A_BYTES;
        const uint32_t blB = st + 2 * A_BYTES + B_BYTES;

#pragma unroll
        for (int s = 0; s < 2; s++) {
            const int kofs = s * 16;
            uint32_t ah[4][4], al[4][4];
#pragma unroll
            for (int fm = 0; fm < 4; fm++) {
                const uint32_t off =
                    (uint32_t)((wm * 64 + fm * 16 + arow) * PADB +
                               (kofs + akc8) * 2);
                ldsm_x4(ah[fm], ahB + off);
                ldsm_x4(al[fm], alB + off);
            }
#pragma unroll
            for (int bi = 0; bi < 4; bi++) {
                uint32_t bh[4], bl[4];
                const uint32_t off =
                    (uint32_t)((wn * 64 + bi * 16 + brow) * PADB +
                               (kofs + bkc8) * 2);
                ldsm_x4(bh, bhB + off);
                ldsm_x4(bl, blB + off);
                // term-major: 8 independent MMAs between same-acc reuse
#pragma unroll
                for (int fm = 0; fm < 4; fm++) {
                    mma16816(acc[fm][2 * bi],     ah[fm], bh);
                    mma16816(acc[fm][2 * bi + 1], ah[fm], bh + 2);
                }
#pragma unroll
                for (int fm = 0; fm < 4; fm++) {
                    mma16816(acc[fm][2 * bi],     ah[fm], bl);
                    mma16816(acc[fm][2 * bi + 1], ah[fm], bl + 2);
                }
#pragma unroll
                for (int fm = 0; fm < 4; fm++) {
                    mma16816(acc[fm][2 * bi],     al[fm], bh);
                    mma16816(acc[fm][2 * bi + 1], al[fm], bh + 2);
                }
            }
        }
        __syncthreads();
    }

    const int r0 = lane >> 2;
    const int c0 = (lane & 3) * 2;
#pragma unroll
    for (int fm = 0; fm < 4; fm++) {
#pragma unroll
        for (int fn = 0; fn < 8; fn++) {
            const size_t row = (size_t)(mBase + wm * 64 + fm * 16 + r0);
            const int col = nBase + wn * 64 + fn * 8 + c0;
            *(float2*)(C + row * N + col) =
                make_float2(acc[fm][fn][0], acc[fm][fn][1]);
            *(float2*)(C + (row + 8) * N + col) =
                make_float2(acc[fm][fn][2], acc[fm][fn][3]);
        }
    }
}

// ---------------------------------------------------------------------------
// Flash attention on tensor cores. Same as R5/R6 but MMA issue reordered
// term-major over bi/j4 pairs (same-acc reuse distance 4).
// ---------------------------------------------------------------------------
#define FQ_BYTES   (128 * 272)
#define FK_BYTES   (64 * 272)
#define FV_BYTES   (128 * 144)
#define FSTAGE     (2 * FK_BYTES + 2 * FV_BYTES)
#define FQ_TOTAL   (2 * FQ_BYTES)
#define FA_SMEM    (FQ_TOTAL + 2 * FSTAGE)

__global__ __launch_bounds__(256, 1) void flash_mma_kernel(
    const __nv_bfloat16* __restrict__ qh, const __nv_bfloat16* __restrict__ ql,
    const __nv_bfloat16* __restrict__ kh, const __nv_bfloat16* __restrict__ kl,
    const __nv_bfloat16* __restrict__ vth, const __nv_bfloat16* __restrict__ vtl,
    float* __restrict__ y)
{
    extern __shared__ char smc[];
    const uint32_t sbase = smem_u32(smc);
    const int tid = threadIdx.x;
    const int lane = tid & 31;
    const int wid = tid >> 5;
    const int b = blockIdx.z, h = blockIdx.y;
    const int bh = b * NH + h;
    const int q0 = blockIdx.x * 128;
    const size_t bT = (size_t)b * TT;
    const int hoff = h * HD;

    {
#pragma unroll
        for (int i = 0; i < 8; i++) {
            int cid = i * 256 + tid;
            int row = cid >> 4, ch = cid & 15;
            const __nv_bfloat16* sq = qh + (bT + q0 + row) * N_EMBD + hoff + ch * 8;
            const __nv_bfloat16* sl = ql + (bT + q0 + row) * N_EMBD + hoff + ch * 8;
            CP_ASYNC16(sbase + row * 272 + ch * 16, sq);
            CP_ASYNC16(sbase + FQ_BYTES + row * 272 + ch * 16, sl);
        }
        CP_COMMIT();
    }

    auto issue_stage = [&](int it, int buf) {
        const uint32_t st = sbase + FQ_TOTAL + buf * FSTAGE;
        const int n0 = it * 64;
#pragma unroll
        for (int i = 0; i < 4; i++) {
            int cid = i * 256 + tid;
            int row = cid >> 4, ch = cid & 15;
            const __nv_bfloat16* sh = kh + (bT + n0 + row) * N_EMBD + hoff + ch * 8;
            const __nv_bfloat16* sl = kl + (bT + n0 + row) * N_EMBD + hoff + ch * 8;
            CP_ASYNC16(st + row * 272 + ch * 16, sh);
            CP_ASYNC16(st + FK_BYTES + row * 272 + ch * 16, sl);
        }
#pragma unroll
        for (int i = 0; i < 4; i++) {
            int cid = i * 256 + tid;
            int row = cid >> 3, ch = cid & 7;
            const __nv_bfloat16* sh = vth + (size_t)(bh * HD + row) * TT + n0 + ch * 8;
            const __nv_bfloat16* sl = vtl + (size_t)(bh * HD + row) * TT + n0 + ch * 8;
            CP_ASYNC16(st + 2 * FK_BYTES + row * 144 + ch * 16, sh);
            CP_ASYNC16(st + 2 * FK_BYTES + FV_BYTES + row * 144 + ch * 16, sl);
        }
    };

    issue_stage(0, 0);
    CP_COMMIT();

    const int arow = (lane & 7) + ((lane >> 3) & 1) * 8;
    const int aoff = (lane >> 4) * 16;
    const int brow = (lane & 7) + ((lane >> 4) & 1) * 8;
    const int boff = ((lane >> 3) & 1) * 16;
    const int g = lane >> 2;
    const int tq = lane & 3;

    float O[16][4];
#pragma unroll
    for (int i = 0; i < 16; i++)
#pragma unroll
        for (int r = 0; r < 4; r++) O[i][r] = 0.0f;
    float ma = -INFINITY, mb = -INFINITY, la = 0.0f, lb = 0.0f;
    const float sc = 0.08838834764831845f;

    const int niter = TT / 64;
    for (int c = 0; c < niter; c++) {
        const int buf = c & 1;
        if (c + 1 < niter) issue_stage(c + 1, (c + 1) & 1);
        CP_COMMIT();
        CP_WAIT1();
        __syncthreads();

        const uint32_t kb = sbase + FQ_TOTAL + buf * FSTAGE;

        float s[8][4];
#pragma unroll
        for (int j = 0; j < 8; j++)
#pragma unroll
            for (int r = 0; r < 4; r++) s[j][r] = 0.0f;

#pragma unroll
        for (int kk = 0; kk < 8; kk++) {
            uint32_t qf[4], qlf[4];
            const uint32_t qo = (wid * 16 + arow) * 272 + kk * 32 + aoff;
            ldsm_x4(qf, sbase + qo);
            ldsm_x4(qlf, sbase + FQ_BYTES + qo);
#pragma unroll
            for (int bp = 0; bp < 2; bp++) {
                uint32_t khf[2][4], klf[2][4];
#pragma unroll
                for (int u = 0; u < 2; u++) {
                    const int bi = 2 * bp + u;
                    const uint32_t ko = (bi * 16 + brow) * 272 + kk * 32 + boff;
                    ldsm_x4(khf[u], kb + ko);
                    ldsm_x4(klf[u], kb + FK_BYTES + ko);
                }
                // term-major, distance 4 between same-acc reuse
#pragma unroll
                for (int u = 0; u < 2; u++) {
                    const int bi = 2 * bp + u;
                    mma16816(s[2 * bi],     qf, khf[u]);
                    mma16816(s[2 * bi + 1], qf, khf[u] + 2);
                }
#pragma unroll
                for (int u = 0; u < 2; u++) {
                    const int bi = 2 * bp + u;
                    mma16816(s[2 * bi],     qf, klf[u]);
                    mma16816(s[2 * bi + 1], qf, klf[u] + 2);
                }
#pragma unroll
                for (int u = 0; u < 2; u++) {
                    const int bi = 2 * bp + u;
                    mma16816(s[2 * bi],     qlf, khf[u]);
                    mma16816(s[2 * bi + 1], qlf, khf[u] + 2);
                }
            }
        }

        float mxa = -INFINITY, mxb = -INFINITY;
#pragma unroll
        for (int j = 0; j < 8; j++) {
            s[j][0] *= sc; s[j][1] *= sc; s[j][2] *= sc; s[j][3] *= sc;
            mxa = fmaxf(mxa, fmaxf(s[j][0], s[j][1]));
            mxb = fmaxf(mxb, fmaxf(s[j][2], s[j][3]));
        }
        mxa = fmaxf(mxa, __shfl_xor_sync(0xffffffffu, mxa, 1));
        mxa = fmaxf(mxa, __shfl_xor_sync(0xffffffffu, mxa, 2));
        mxb = fmaxf(mxb, __shfl_xor_sync(0xffffffffu, mxb, 1));
        mxb = fmaxf(mxb, __shfl_xor_sync(0xffffffffu, mxb, 2));
        float mna = fmaxf(ma, mxa), mnb = fmaxf(mb, mxb);
        float alpha = __expf(ma - mna), beta = __expf(mb - mnb);
        ma = mna; mb = mnb;
        float sua = 0.0f, sub = 0.0f;
#pragma unroll
        for (int j = 0; j < 8; j++) {
            s[j][0] = __expf(s[j][0] - mna);
            s[j][1] = __expf(s[j][1] - mna);
            s[j][2] = __expf(s[j][2] - mnb);
            s[j][3] = __expf(s[j][3] - mnb);
            sua += s[j][0] + s[j][1];
            sub += s[j][2] + s[j][3];
        }
        sua += __shfl_xor_sync(0xffffffffu, sua, 1);
        sua += __shfl_xor_sync(0xffffffffu, sua, 2);
        sub += __shfl_xor_sync(0xffffffffu, sub, 1);
        sub += __shfl_xor_sync(0xffffffffu, sub, 2);
        la = la * alpha + sua;
        lb = lb * beta + sub;
#pragma unroll
        for (int j2 = 0; j2 < 16; j2++) {
            O[j2][0] *= alpha; O[j2][1] *= alpha;
            O[j2][2] *= beta;  O[j2][3] *= beta;
        }

        uint32_t Ph[4][4], Pl[4][4];
#pragma unroll
        for (int kp = 0; kp < 4; kp++) {
            pack_hl(s[2 * kp][0],     s[2 * kp][1],     Ph[kp][0], Pl[kp][0]);
            pack_hl(s[2 * kp][2],     s[2 * kp][3],     Ph[kp][1], Pl[kp][1]);
            pack_hl(s[2 * kp + 1][0], s[2 * kp + 1][1], Ph[kp][2], Pl[kp][2]);
            pack_hl(s[2 * kp + 1][2], s[2 * kp + 1][3], Ph[kp][3], Pl[kp][3]);
        }

        const uint32_t vb = kb + 2 * FK_BYTES;
#pragma unroll
        for (int kp = 0; kp < 4; kp++) {
#pragma unroll
            for (int jp = 0; jp < 4; jp++) {
                uint32_t vhf[2][4], vlf[2][4];
#pragma unroll
                for (int u = 0; u < 2; u++) {
                    const int j4 = 2 * jp + u;
                    const uint32_t vo = (j4 * 16 + brow) * 144 + kp * 32 + boff;
                    ldsm_x4(vhf[u], vb + vo);
                    ldsm_x4(vlf[u], vb + FV_BYTES + vo);
                }
                // term-major, distance 4
#pragma unroll
                for (int u = 0; u < 2; u++) {
                    const int j4 = 2 * jp + u;
                    mma16816(O[2 * j4],     Ph[kp], vhf[u]);
                    mma16816(O[2 * j4 + 1], Ph[kp], vhf[u] + 2);
                }
#pragma unroll
                for (int u = 0; u < 2; u++) {
                    const int j4 = 2 * jp + u;
                    mma16816(O[2 * j4],     Ph[kp], vlf[u]);
                    mma16816(O[2 * j4 + 1], Ph[kp], vlf[u] + 2);
                }
#pragma unroll
                for (int u = 0; u < 2; u++) {
                    const int j4 = 2 * jp + u;
                    mma16816(O[2 * j4],     Pl[kp], vhf[u]);
                    mma16816(O[2 * j4 + 1], Pl[kp], vhf[u] + 2);
                }
            }
        }
        __syncthreads();
    }

    const float inva = 1.0f / la, invb = 1.0f / lb;
    const size_t rowa = bT + q0 + wid * 16 + g;
    const size_t rowb = rowa + 8;
#pragma unroll
    for (int j2 = 0; j2 < 16; j2++) {
        const int col = hoff + j2 * 8 + tq * 2;
        *(float2*)(y + rowa * N_EMBD + col) =
            make_float2(O[j2][0] * inva, O[j2][1] * inva);
        *(float2*)(y + rowb * N_EMBD + col) =
            make_float2(O[j2][2] * invb, O[j2][3] * invb);
    }
}

// ---------------------------------------------------------------------------
// Launch
// ---------------------------------------------------------------------------
extern "C" void kernel_launch(void* const* d_in, const int* in_sizes, int n_in,
                              void* d_out, int out_size)
{
    const float* x      = (const float*)d_in[0];
    const float* w_attn = (const float*)d_in[1];
    const float* w_proj = (const float*)d_in[2];
    float* out = (float*)d_out;

    float *qkv = nullptr, *y = nullptr;
    __nv_bfloat16 *Ah, *Al, *Bh, *Bl, *Vth, *Vtl;
    cudaGetSymbolAddress((void**)&qkv, g_qkv);
    cudaGetSymbolAddress((void**)&y, g_y);
    cudaGetSymbolAddress((void**)&Ah, g_Ah);
    cudaGetSymbolAddress((void**)&Al, g_Al);
    cudaGetSymbolAddress((void**)&Bh, g_Bh);
    cudaGetSymbolAddress((void**)&Bl, g_Bl);
    cudaGetSymbolAddress((void**)&Vth, g_Vth);
    cudaGetSymbolAddress((void**)&Vtl, g_Vtl);

    cudaFuncSetAttribute(gemm_mma_kernel,
                         cudaFuncAttributeMaxDynamicSharedMemorySize, GEMM_SMEM);
    cudaFuncSetAttribute(flash_mma_kernel,
                         cudaFuncAttributeMaxDynamicSharedMemorySize, FA_SMEM);

    const int n4 = MROWS * N_EMBD / 4;

    // 1. RoPE table
    rope_table_kernel<<<(TT * 64 + 255) / 256, 256>>>();

    // 2. Split-convert x and w_attn^T
    conv_rm_kernel<<<(n4 + 255) / 256, 256>>>(x, Ah, Al, n4);
    conv_tr_kernel<<<dim3(QKV_N / 32, N_EMBD / 32), dim3(32, 8)>>>(
        w_attn, Bh, Bl, N_EMBD, QKV_N);

    // 3. QKV projection
    gemm_mma_kernel<<<dim3(QKV_N / BN, MROWS / BM), 256, GEMM_SMEM>>>(
        Ah, Al, Bh, Bl, qkv, MROWS, QKV_N, N_EMBD);

    // 4. RoPE + split q -> Ah/Al, k -> Bh/Bl; transpose-split v -> Vth/Vtl
    conv_rope_kernel<<<(MROWS * 512 + 255) / 256, 256>>>(qkv, 0, Ah, Al);
    conv_rope_kernel<<<(MROWS * 512 + 255) / 256, 256>>>(qkv, N_EMBD, Bh, Bl);
    conv_vt_kernel<<<dim3(TT / 32, HD / 32, BB * NH), dim3(32, 8)>>>(qkv, Vth, Vtl);

    // 5. Flash attention on tensor cores -> g_y
    flash_mma_kernel<<<dim3(TT / 128, NH, BB), 256, FA_SMEM>>>(
        Ah, Al, Bh, Bl, Vth, Vtl, y);

    // 6. Split-convert y and w_proj^T (reuse Ah/Al, Bh/Bl)
    conv_rm_kernel<<<(n4 + 255) / 256, 256>>>(y, Ah, Al, n4);
    conv_tr_kernel<<<dim3(N_EMBD / 32, N_EMBD / 32), dim3(32, 8)>>>(
        w_proj, Bh, Bl, N_EMBD, N_EMBD);

    // 7. Output projection
    gemm_mma_kernel<<<dim3(N_EMBD / BN, MROWS / BM), 256, GEMM_SMEM>>>(
        Ah, Al, Bh, Bl, out, MROWS, N_EMBD, N_EMBD);
}

// round 9
// speedup vs baseline: 1.0250x; 1.0250x over previous
#include <cuda_runtime.h>
#include <cuda_bf16.h>
#include <stdint.h>
#include <math.h>

// ---------------------------------------------------------------------------
// Problem constants
// ---------------------------------------------------------------------------
#define N_EMBD 2048
#define NH     16
#define HD     128
#define TT     2048         // seq len
#define BB     2            // batch
#define MROWS  (BB * TT)    // 4096 flattened (b, t) rows
#define QKV_N  (3 * N_EMBD) // 6144

// ---------------------------------------------------------------------------
// Scratch (no cudaMalloc allowed -> static __device__ globals)
// ---------------------------------------------------------------------------
__device__ float g_qkv[(size_t)MROWS * QKV_N];   // 100.7 MB
__device__ float g_y[(size_t)MROWS * N_EMBD];    //  33.6 MB
__device__ float g_cos[TT * (HD / 2)];
__device__ float g_sin[TT * (HD / 2)];
// bf16 hi/lo split operands (multi-purpose, reused across phases)
__device__ __nv_bfloat16 g_Ah[(size_t)MROWS * N_EMBD];   // x-split / q-split / y-split
__device__ __nv_bfloat16 g_Al[(size_t)MROWS * N_EMBD];
__device__ __nv_bfloat16 g_Bh[(size_t)QKV_N * N_EMBD];   // w_attn^T / k-split / w_proj^T
__device__ __nv_bfloat16 g_Bl[(size_t)QKV_N * N_EMBD];
__device__ __nv_bfloat16 g_Vth[(size_t)MROWS * N_EMBD];  // V^T per head [bh][d][t]
__device__ __nv_bfloat16 g_Vtl[(size_t)MROWS * N_EMBD];

// ---------------------------------------------------------------------------
// Helpers (plain sm_103-legal PTX only: ldmatrix / mma.sync / cp.async)
// ---------------------------------------------------------------------------
__device__ __forceinline__ uint32_t smem_u32(const void* p) {
    uint32_t a;
    asm("{ .reg .u64 t; cvta.to.shared.u64 t, %1; cvt.u32.u64 %0, t; }"
        : "=r"(a) : "l"(p));
    return a;
}

__device__ __forceinline__ void ldsm_x4(uint32_t* r, uint32_t addr) {
    asm volatile("ldmatrix.sync.aligned.m8n8.x4.shared.b16 {%0,%1,%2,%3}, [%4];"
                 : "=r"(r[0]), "=r"(r[1]), "=r"(r[2]), "=r"(r[3]) : "r"(addr));
}

__device__ __forceinline__ void mma16816(float* c, const uint32_t* a,
                                         const uint32_t* b) {
    asm volatile(
        "mma.sync.aligned.m16n8k16.row.col.f32.bf16.bf16.f32 "
        "{%0,%1,%2,%3}, {%4,%5,%6,%7}, {%8,%9}, {%0,%1,%2,%3};"
        : "+f"(c[0]), "+f"(c[1]), "+f"(c[2]), "+f"(c[3])
        : "r"(a[0]), "r"(a[1]), "r"(a[2]), "r"(a[3]), "r"(b[0]), "r"(b[1]));
}

#define CP_ASYNC16(dst, src) \
    asm volatile("cp.async.cg.shared.global [%0], [%1], 16;" \
                 :: "r"(dst), "l"(src) : "memory")
#define CP_COMMIT() asm volatile("cp.async.commit_group;" ::: "memory")
#define CP_WAIT1()  asm volatile("cp.async.wait_group 1;" ::: "memory")

__device__ __forceinline__ void split2(float x, __nv_bfloat16& h, __nv_bfloat16& l) {
    h = __float2bfloat16(x);
    l = __float2bfloat16(x - __bfloat162float(h));
}

// pack two floats into bf16x2 hi + residual bf16x2 lo
__device__ __forceinline__ void pack_hl(float x, float y, uint32_t& h, uint32_t& l) {
    __nv_bfloat162 hh = __floats2bfloat162_rn(x, y);
    float rx = x - __bfloat162float(hh.x);
    float ry = y - __bfloat162float(hh.y);
    __nv_bfloat162 ll = __floats2bfloat162_rn(rx, ry);
    h = *(uint32_t*)&hh;
    l = *(uint32_t*)&ll;
}

// ---------------------------------------------------------------------------
// Convert kernels
// ---------------------------------------------------------------------------
__global__ void conv_rm_kernel(const float* __restrict__ in,
                               __nv_bfloat16* __restrict__ oh,
                               __nv_bfloat16* __restrict__ ol, int n4) {
    int idx = blockIdx.x * blockDim.x + threadIdx.x;
    if (idx >= n4) return;
    float4 v = ((const float4*)in)[idx];
    __nv_bfloat16 h0, h1, h2, h3, l0, l1, l2, l3;
    split2(v.x, h0, l0); split2(v.y, h1, l1);
    split2(v.z, h2, l2); split2(v.w, h3, l3);
    ((__nv_bfloat162*)oh)[idx * 2]     = __halves2bfloat162(h0, h1);
    ((__nv_bfloat162*)oh)[idx * 2 + 1] = __halves2bfloat162(h2, h3);
    ((__nv_bfloat162*)ol)[idx * 2]     = __halves2bfloat162(l0, l1);
    ((__nv_bfloat162*)ol)[idx * 2 + 1] = __halves2bfloat162(l2, l3);
}

// B[K][N] fp32 row-major -> BT[N][K] bf16 hi/lo
__global__ void conv_tr_kernel(const float* __restrict__ B,
                               __nv_bfloat16* __restrict__ bh,
                               __nv_bfloat16* __restrict__ bl, int K, int N) {
    __shared__ float tile[32][33];
    int n0 = blockIdx.x * 32, k0 = blockIdx.y * 32;
    int tx = threadIdx.x, ty = threadIdx.y;
#pragma unroll
    for (int i = 0; i < 4; i++)
        tile[ty + i * 8][tx] = B[(size_t)(k0 + ty + i * 8) * N + n0 + tx];
    __syncthreads();
#pragma unroll
    for (int i = 0; i < 4; i++) {
        int n = ty + i * 8;
        float v = tile[tx][n];
        __nv_bfloat16 h, l;
        split2(v, h, l);
        size_t o = (size_t)(n0 + n) * K + k0 + tx;
        bh[o] = h;
        bl[o] = l;
    }
}

// q or k section of g_qkv: apply RoPE + split to bf16 hi/lo [m][2048]
__global__ void conv_rope_kernel(const float* __restrict__ qkv, int secOff,
                                 __nv_bfloat16* __restrict__ oh,
                                 __nv_bfloat16* __restrict__ ol) {
    int idx = blockIdx.x * blockDim.x + threadIdx.x;
    if (idx >= MROWS * 512) return;
    int m = idx >> 9;
    int col = (idx & 511) * 4;
    int t = m & (TT - 1);
    int i0 = (col & 127) >> 1;
    float4 v = *(const float4*)(qkv + (size_t)m * QKV_N + secOff + col);
    float c0 = g_cos[t * 64 + i0],     s0 = g_sin[t * 64 + i0];
    float c1 = g_cos[t * 64 + i0 + 1], s1 = g_sin[t * 64 + i0 + 1];
    float r0 = v.x * c0 - v.y * s0;
    float r1 = v.y * c0 + v.x * s0;
    float r2 = v.z * c1 - v.w * s1;
    float r3 = v.w * c1 + v.z * s1;
    __nv_bfloat16 h0, h1, h2, h3, l0, l1, l2, l3;
    split2(r0, h0, l0); split2(r1, h1, l1);
    split2(r2, h2, l2); split2(r3, h3, l3);
    size_t o = (size_t)m * N_EMBD + col;
    *(__nv_bfloat162*)(oh + o)     = __halves2bfloat162(h0, h1);
    *(__nv_bfloat162*)(oh + o + 2) = __halves2bfloat162(h2, h3);
    *(__nv_bfloat162*)(ol + o)     = __halves2bfloat162(l0, l1);
    *(__nv_bfloat162*)(ol + o + 2) = __halves2bfloat162(l2, l3);
}

// V section of g_qkv -> per-head transposed bf16 hi/lo: vt[(bh*128+d)*2048 + t]
__global__ void conv_vt_kernel(const float* __restrict__ qkv,
                               __nv_bfloat16* __restrict__ vh,
                               __nv_bfloat16* __restrict__ vl) {
    __shared__ float tile[32][33];
    int bh = blockIdx.z;
    int b = bh >> 4, h = bh & 15;
    int t0 = blockIdx.x * 32, d0 = blockIdx.y * 32;
    int tx = threadIdx.x, ty = threadIdx.y;
#pragma unroll
    for (int i = 0; i < 4; i++)
        tile[ty + i * 8][tx] =
            qkv[(size_t)(b * TT + t0 + ty + i * 8) * QKV_N + 2 * N_EMBD + h * HD + d0 + tx];
    __syncthreads();
#pragma unroll
    for (int i = 0; i < 4; i++) {
        int d = ty + i * 8;
        float v = tile[tx][d];
        __nv_bfloat16 hh, ll;
        split2(v, hh, ll);
        size_t o = (size_t)(bh * HD + d0 + d) * TT + t0 + tx;
        vh[o] = hh;
        vl[o] = ll;
    }
}

// ---------------------------------------------------------------------------
// RoPE table
// ---------------------------------------------------------------------------
__global__ void rope_table_kernel() {
    int idx = blockIdx.x * blockDim.x + threadIdx.x;
    if (idx >= TT * 64) return;
    int t = idx >> 6;
    int i = idx & 63;
    double theta = pow(10000.0, -(double)i / 64.0);
    double ang = (double)t * theta;
    g_cos[idx] = (float)cos(ang);
    g_sin[idx] = (float)sin(ang);
}

// ---------------------------------------------------------------------------
// Tensor-core GEMM via mma.sync. CTA tile 128x256, BK=32, **16 warps**
// (512 threads -> 4 warps per SMSP), warp tile 32x64. Tests the hypothesis
// that the fallback-HMMA pipe needs 4 warps/SMSP to saturate.
// ---------------------------------------------------------------------------
#define BM 128
#define BN 256
#define BK 32
#define PADB 80
#define A_BYTES (128 * PADB)
#define B_BYTES (256 * PADB)
#define STG_BYTES (2 * A_BYTES + 2 * B_BYTES)   // 61440
#define GEMM_SMEM (2 * STG_BYTES)               // 122880

__global__ __launch_bounds__(512, 1) void gemm_mma_kernel(
    const __nv_bfloat16* __restrict__ Ah, const __nv_bfloat16* __restrict__ Al,
    const __nv_bfloat16* __restrict__ Bh, const __nv_bfloat16* __restrict__ Bl,
    float* __restrict__ C, int M, int N, int K)
{
    extern __shared__ char smc[];
    const uint32_t sbase = smem_u32(smc);
    const int tid = threadIdx.x;
    const int lane = tid & 31;
    const int wid = tid >> 5;
    const int wm = wid & 3;            // 4 warps in M (32 rows each)
    const int wn = wid >> 2;           // 4 warps in N (64 cols each)
    const int mBase = blockIdx.y * BM;
    const int nBase = blockIdx.x * BN;
    const int nch = K / BK;

    const int ldRow = tid >> 2;        // 0..127
    const int ldCh  = tid & 3;         // 16B chunk within 64B of K-row

    float acc[2][8][4];
#pragma unroll
    for (int i = 0; i < 2; i++)
#pragma unroll
        for (int j = 0; j < 8; j++)
#pragma unroll
            for (int r = 0; r < 4; r++) acc[i][j][r] = 0.0f;

    // stage loader: 6 x 16B cp.async per thread (512 threads)
    auto issue_stage = [&](int c, int buf) {
        const uint32_t st = sbase + buf * STG_BYTES;
        const int kOff = c * BK;
        const uint32_t so = ldRow * PADB + ldCh * 16;
        CP_ASYNC16(st + so,
                   Ah + (size_t)(mBase + ldRow) * K + kOff + ldCh * 8);
        CP_ASYNC16(st + A_BYTES + so,
                   Al + (size_t)(mBase + ldRow) * K + kOff + ldCh * 8);
#pragma unroll
        for (int i = 0; i < 2; i++) {
            const int row = i * 128 + ldRow;
            const uint32_t so2 = row * PADB + ldCh * 16;
            CP_ASYNC16(st + 2 * A_BYTES + so2,
                       Bh + (size_t)(nBase + row) * K + kOff + ldCh * 8);
            CP_ASYNC16(st + 2 * A_BYTES + B_BYTES + so2,
                       Bl + (size_t)(nBase + row) * K + kOff + ldCh * 8);
        }
    };

    issue_stage(0, 0);
    CP_COMMIT();

    const int arow = (lane & 7) + ((lane >> 3) & 1) * 8;
    const int akc8 = (lane >> 4) * 8;
    const int brow = (lane & 7) + ((lane >> 4) & 1) * 8;
    const int bkc8 = ((lane >> 3) & 1) * 8;

    for (int c = 0; c < nch; c++) {
        const int buf = c & 1;
        if (c + 1 < nch) issue_stage(c + 1, (c + 1) & 1);
        CP_COMMIT();
        CP_WAIT1();
        __syncthreads();

        const uint32_t st = sbase + buf * STG_BYTES;
        const uint32_t ahB = st;
        const uint32_t alB = st + A_BYTES;
        const uint32_t bhB = st + 2 * A_BYTES;
        const uint32_t blB = st + 2 * A_BYTES + B_BYTES;

#pragma unroll
        for (int s = 0; s < 2; s++) {
            const int kofs = s * 16;
            uint32_t ah[2][4], al[2][4];
#pragma unroll
            for (int fm = 0; fm < 2; fm++) {
                const uint32_t off =
                    (uint32_t)((wm * 32 + fm * 16 + arow) * PADB +
                               (kofs + akc8) * 2);
                ldsm_x4(ah[fm], ahB + off);
                ldsm_x4(al[fm], alB + off);
            }
#pragma unroll
            for (int bi = 0; bi < 4; bi++) {
                uint32_t bh[4], bl[4];
                const uint32_t off =
                    (uint32_t)((wn * 64 + bi * 16 + brow) * PADB +
                               (kofs + bkc8) * 2);
                ldsm_x4(bh, bhB + off);
                ldsm_x4(bl, blB + off);
#pragma unroll
                for (int fm = 0; fm < 2; fm++) {
                    mma16816(acc[fm][2 * bi],     ah[fm], bh);
                    mma16816(acc[fm][2 * bi + 1], ah[fm], bh + 2);
                }
#pragma unroll
                for (int fm = 0; fm < 2; fm++) {
                    mma16816(acc[fm][2 * bi],     ah[fm], bl);
                    mma16816(acc[fm][2 * bi + 1], ah[fm], bl + 2);
                }
#pragma unroll
                for (int fm = 0; fm < 2; fm++) {
                    mma16816(acc[fm][2 * bi],     al[fm], bh);
                    mma16816(acc[fm][2 * bi + 1], al[fm], bh + 2);
                }
            }
        }
        __syncthreads();
    }

    const int r0 = lane >> 2;
    const int c0 = (lane & 3) * 2;
#pragma unroll
    for (int fm = 0; fm < 2; fm++) {
#pragma unroll
        for (int fn = 0; fn < 8; fn++) {
            const size_t row = (size_t)(mBase + wm * 32 + fm * 16 + r0);
            const int col = nBase + wn * 64 + fn * 8 + c0;
            *(float2*)(C + row * N + col) =
                make_float2(acc[fm][fn][0], acc[fm][fn][1]);
            *(float2*)(C + (row + 8) * N + col) =
                make_float2(acc[fm][fn][2], acc[fm][fn][3]);
        }
    }
}

// ---------------------------------------------------------------------------
// Flash attention on tensor cores (unchanged from R7 / best-known).
// ---------------------------------------------------------------------------
#define FQ_BYTES   (128 * 272)
#define FK_BYTES   (64 * 272)
#define FV_BYTES   (128 * 144)
#define FSTAGE     (2 * FK_BYTES + 2 * FV_BYTES)
#define FQ_TOTAL   (2 * FQ_BYTES)
#define FA_SMEM    (FQ_TOTAL + 2 * FSTAGE)

__global__ __launch_bounds__(256, 1) void flash_mma_kernel(
    const __nv_bfloat16* __restrict__ qh, const __nv_bfloat16* __restrict__ ql,
    const __nv_bfloat16* __restrict__ kh, const __nv_bfloat16* __restrict__ kl,
    const __nv_bfloat16* __restrict__ vth, const __nv_bfloat16* __restrict__ vtl,
    float* __restrict__ y)
{
    extern __shared__ char smc[];
    const uint32_t sbase = smem_u32(smc);
    const int tid = threadIdx.x;
    const int lane = tid & 31;
    const int wid = tid >> 5;
    const int b = blockIdx.z, h = blockIdx.y;
    const int bh = b * NH + h;
    const int q0 = blockIdx.x * 128;
    const size_t bT = (size_t)b * TT;
    const int hoff = h * HD;

    {
#pragma unroll
        for (int i = 0; i < 8; i++) {
            int cid = i * 256 + tid;
            int row = cid >> 4, ch = cid & 15;
            const __nv_bfloat16* sq = qh + (bT + q0 + row) * N_EMBD + hoff + ch * 8;
            const __nv_bfloat16* sl = ql + (bT + q0 + row) * N_EMBD + hoff + ch * 8;
            CP_ASYNC16(sbase + row * 272 + ch * 16, sq);
            CP_ASYNC16(sbase + FQ_BYTES + row * 272 + ch * 16, sl);
        }
        CP_COMMIT();
    }

    auto issue_stage = [&](int it, int buf) {
        const uint32_t st = sbase + FQ_TOTAL + buf * FSTAGE;
        const int n0 = it * 64;
#pragma unroll
        for (int i = 0; i < 4; i++) {
            int cid = i * 256 + tid;
            int row = cid >> 4, ch = cid & 15;
            const __nv_bfloat16* sh = kh + (bT + n0 + row) * N_EMBD + hoff + ch * 8;
            const __nv_bfloat16* sl = kl + (bT + n0 + row) * N_EMBD + hoff + ch * 8;
            CP_ASYNC16(st + row * 272 + ch * 16, sh);
            CP_ASYNC16(st + FK_BYTES + row * 272 + ch * 16, sl);
        }
#pragma unroll
        for (int i = 0; i < 4; i++) {
            int cid = i * 256 + tid;
            int row = cid >> 3, ch = cid & 7;
            const __nv_bfloat16* sh = vth + (size_t)(bh * HD + row) * TT + n0 + ch * 8;
            const __nv_bfloat16* sl = vtl + (size_t)(bh * HD + row) * TT + n0 + ch * 8;
            CP_ASYNC16(st + 2 * FK_BYTES + row * 144 + ch * 16, sh);
            CP_ASYNC16(st + 2 * FK_BYTES + FV_BYTES + row * 144 + ch * 16, sl);
        }
    };

    issue_stage(0, 0);
    CP_COMMIT();

    const int arow = (lane & 7) + ((lane >> 3) & 1) * 8;
    const int aoff = (lane >> 4) * 16;
    const int brow = (lane & 7) + ((lane >> 4) & 1) * 8;
    const int boff = ((lane >> 3) & 1) * 16;
    const int g = lane >> 2;
    const int tq = lane & 3;

    float O[16][4];
#pragma unroll
    for (int i = 0; i < 16; i++)
#pragma unroll
        for (int r = 0; r < 4; r++) O[i][r] = 0.0f;
    float ma = -INFINITY, mb = -INFINITY, la = 0.0f, lb = 0.0f;
    const float sc = 0.08838834764831845f;

    const int niter = TT / 64;
    for (int c = 0; c < niter; c++) {
        const int buf = c & 1;
        if (c + 1 < niter) issue_stage(c + 1, (c + 1) & 1);
        CP_COMMIT();
        CP_WAIT1();
        __syncthreads();

        const uint32_t kb = sbase + FQ_TOTAL + buf * FSTAGE;

        float s[8][4];
#pragma unroll
        for (int j = 0; j < 8; j++)
#pragma unroll
            for (int r = 0; r < 4; r++) s[j][r] = 0.0f;

#pragma unroll
        for (int kk = 0; kk < 8; kk++) {
            uint32_t qf[4], qlf[4];
            const uint32_t qo = (wid * 16 + arow) * 272 + kk * 32 + aoff;
            ldsm_x4(qf, sbase + qo);
            ldsm_x4(qlf, sbase + FQ_BYTES + qo);
#pragma unroll
            for (int bp = 0; bp < 2; bp++) {
                uint32_t khf[2][4], klf[2][4];
#pragma unroll
                for (int u = 0; u < 2; u++) {
                    const int bi = 2 * bp + u;
                    const uint32_t ko = (bi * 16 + brow) * 272 + kk * 32 + boff;
                    ldsm_x4(khf[u], kb + ko);
                    ldsm_x4(klf[u], kb + FK_BYTES + ko);
                }
#pragma unroll
                for (int u = 0; u < 2; u++) {
                    const int bi = 2 * bp + u;
                    mma16816(s[2 * bi],     qf, khf[u]);
                    mma16816(s[2 * bi + 1], qf, khf[u] + 2);
                }
#pragma unroll
                for (int u = 0; u < 2; u++) {
                    const int bi = 2 * bp + u;
                    mma16816(s[2 * bi],     qf, klf[u]);
                    mma16816(s[2 * bi + 1], qf, klf[u] + 2);
                }
#pragma unroll
                for (int u = 0; u < 2; u++) {
                    const int bi = 2 * bp + u;
                    mma16816(s[2 * bi],     qlf, khf[u]);
                    mma16816(s[2 * bi + 1], qlf, khf[u] + 2);
                }
            }
        }

        float mxa = -INFINITY, mxb = -INFINITY;
#pragma unroll
        for (int j = 0; j < 8; j++) {
            s[j][0] *= sc; s[j][1] *= sc; s[j][2] *= sc; s[j][3] *= sc;
            mxa = fmaxf(mxa, fmaxf(s[j][0], s[j][1]));
            mxb = fmaxf(mxb, fmaxf(s[j][2], s[j][3]));
        }
        mxa = fmaxf(mxa, __shfl_xor_sync(0xffffffffu, mxa, 1));
        mxa = fmaxf(mxa, __shfl_xor_sync(0xffffffffu, mxa, 2));
        mxb = fmaxf(mxb, __shfl_xor_sync(0xffffffffu, mxb, 1));
        mxb = fmaxf(mxb, __shfl_xor_sync(0xffffffffu, mxb, 2));
        float mna = fmaxf(ma, mxa), mnb = fmaxf(mb, mxb);
        float alpha = __expf(ma - mna), beta = __expf(mb - mnb);
        ma = mna; mb = mnb;
        float sua = 0.0f, sub = 0.0f;
#pragma unroll
        for (int j = 0; j < 8; j++) {
            s[j][0] = __expf(s[j][0] - mna);
            s[j][1] = __expf(s[j][1] - mna);
            s[j][2] = __expf(s[j][2] - mnb);
            s[j][3] = __expf(s[j][3] - mnb);
            sua += s[j][0] + s[j][1];
            sub += s[j][2] + s[j][3];
        }
        sua += __shfl_xor_sync(0xffffffffu, sua, 1);
        sua += __shfl_xor_sync(0xffffffffu, sua, 2);
        sub += __shfl_xor_sync(0xffffffffu, sub, 1);
        sub += __shfl_xor_sync(0xffffffffu, sub, 2);
        la = la * alpha + sua;
        lb = lb * beta + sub;
#pragma unroll
        for (int j2 = 0; j2 < 16; j2++) {
            O[j2][0] *= alpha; O[j2][1] *= alpha;
            O[j2][2] *= beta;  O[j2][3] *= beta;
        }

        uint32_t Ph[4][4], Pl[4][4];
#pragma unroll
        for (int kp = 0; kp < 4; kp++) {
            pack_hl(s[2 * kp][0],     s[2 * kp][1],     Ph[kp][0], Pl[kp][0]);
            pack_hl(s[2 * kp][2],     s[2 * kp][3],     Ph[kp][1], Pl[kp][1]);
            pack_hl(s[2 * kp + 1][0], s[2 * kp + 1][1], Ph[kp][2], Pl[kp][2]);
            pack_hl(s[2 * kp + 1][2], s[2 * kp + 1][3], Ph[kp][3], Pl[kp][3]);
        }

        const uint32_t vb = kb + 2 * FK_BYTES;
#pragma unroll
        for (int kp = 0; kp < 4; kp++) {
#pragma unroll
            for (int jp = 0; jp < 4; jp++) {
                uint32_t vhf[2][4], vlf[2][4];
#pragma unroll
                for (int u = 0; u < 2; u++) {
                    const int j4 = 2 * jp + u;
                    const uint32_t vo = (j4 * 16 + brow) * 144 + kp * 32 + boff;
                    ldsm_x4(vhf[u], vb + vo);
                    ldsm_x4(vlf[u], vb + FV_BYTES + vo);
                }
#pragma unroll
                for (int u = 0; u < 2; u++) {
                    const int j4 = 2 * jp + u;
                    mma16816(O[2 * j4],     Ph[kp], vhf[u]);
                    mma16816(O[2 * j4 + 1], Ph[kp], vhf[u] + 2);
                }
#pragma unroll
                for (int u = 0; u < 2; u++) {
                    const int j4 = 2 * jp + u;
                    mma16816(O[2 * j4],     Ph[kp], vlf[u]);
                    mma16816(O[2 * j4 + 1], Ph[kp], vlf[u] + 2);
                }
#pragma unroll
                for (int u = 0; u < 2; u++) {
                    const int j4 = 2 * jp + u;
                    mma16816(O[2 * j4],     Pl[kp], vhf[u]);
                    mma16816(O[2 * j4 + 1], Pl[kp], vhf[u] + 2);
                }
            }
        }
        __syncthreads();
    }

    const float inva = 1.0f / la, invb = 1.0f / lb;
    const size_t rowa = bT + q0 + wid * 16 + g;
    const size_t rowb = rowa + 8;
#pragma unroll
    for (int j2 = 0; j2 < 16; j2++) {
        const int col = hoff + j2 * 8 + tq * 2;
        *(float2*)(y + rowa * N_EMBD + col) =
            make_float2(O[j2][0] * inva, O[j2][1] * inva);
        *(float2*)(y + rowb * N_EMBD + col) =
            make_float2(O[j2][2] * invb, O[j2][3] * invb);
    }
}

// ---------------------------------------------------------------------------
// Launch
// ---------------------------------------------------------------------------
extern "C" void kernel_launch(void* const* d_in, const int* in_sizes, int n_in,
                              void* d_out, int out_size)
{
    const float* x      = (const float*)d_in[0];
    const float* w_attn = (const float*)d_in[1];
    const float* w_proj = (const float*)d_in[2];
    float* out = (float*)d_out;

    float *qkv = nullptr, *y = nullptr;
    __nv_bfloat16 *Ah, *Al, *Bh, *Bl, *Vth, *Vtl;
    cudaGetSymbolAddress((void**)&qkv, g_qkv);
    cudaGetSymbolAddress((void**)&y, g_y);
    cudaGetSymbolAddress((void**)&Ah, g_Ah);
    cudaGetSymbolAddress((void**)&Al, g_Al);
    cudaGetSymbolAddress((void**)&Bh, g_Bh);
    cudaGetSymbolAddress((void**)&Bl, g_Bl);
    cudaGetSymbolAddress((void**)&Vth, g_Vth);
    cudaGetSymbolAddress((void**)&Vtl, g_Vtl);

    cudaFuncSetAttribute(gemm_mma_kernel,
                         cudaFuncAttributeMaxDynamicSharedMemorySize, GEMM_SMEM);
    cudaFuncSetAttribute(flash_mma_kernel,
                         cudaFuncAttributeMaxDynamicSharedMemorySize, FA_SMEM);

    const int n4 = MROWS * N_EMBD / 4;

    // 1. RoPE table
    rope_table_kernel<<<(TT * 64 + 255) / 256, 256>>>();

    // 2. Split-convert x and w_attn^T
    conv_rm_kernel<<<(n4 + 255) / 256, 256>>>(x, Ah, Al, n4);
    conv_tr_kernel<<<dim3(QKV_N / 32, N_EMBD / 32), dim3(32, 8)>>>(
        w_attn, Bh, Bl, N_EMBD, QKV_N);

    // 3. QKV projection (512-thread CTAs, 4 warps/SMSP)
    gemm_mma_kernel<<<dim3(QKV_N / BN, MROWS / BM), 512, GEMM_SMEM>>>(
        Ah, Al, Bh, Bl, qkv, MROWS, QKV_N, N_EMBD);

    // 4. RoPE + split q -> Ah/Al, k -> Bh/Bl; transpose-split v -> Vth/Vtl
    conv_rope_kernel<<<(MROWS * 512 + 255) / 256, 256>>>(qkv, 0, Ah, Al);
    conv_rope_kernel<<<(MROWS * 512 + 255) / 256, 256>>>(qkv, N_EMBD, Bh, Bl);
    conv_vt_kernel<<<dim3(TT / 32, HD / 32, BB * NH), dim3(32, 8)>>>(qkv, Vth, Vtl);

    // 5. Flash attention on tensor cores -> g_y
    flash_mma_kernel<<<dim3(TT / 128, NH, BB), 256, FA_SMEM>>>(
        Ah, Al, Bh, Bl, Vth, Vtl, y);

    // 6. Split-convert y and w_proj^T (reuse Ah/Al, Bh/Bl)
    conv_rm_kernel<<<(n4 + 255) / 256, 256>>>(y, Ah, Al, n4);
    conv_tr_kernel<<<dim3(N_EMBD / 32, N_EMBD / 32), dim3(32, 8)>>>(
        w_proj, Bh, Bl, N_EMBD, N_EMBD);

    // 7. Output projection
    gemm_mma_kernel<<<dim3(N_EMBD / BN, MROWS / BM), 512, GEMM_SMEM>>>(
        Ah, Al, Bh, Bl, out, MROWS, N_EMBD, N_EMBD);
}

// round 10
// speedup vs baseline: 1.4463x; 1.4110x over previous
#include <cuda_runtime.h>
#include <cuda_fp16.h>
#include <stdint.h>
#include <math.h>

// ---------------------------------------------------------------------------
// Problem constants
// ---------------------------------------------------------------------------
#define N_EMBD 2048
#define NH     16
#define HD     128
#define TT     2048         // seq len
#define BB     2            // batch
#define MROWS  (BB * TT)    // 4096 flattened (b, t) rows
#define QKV_N  (3 * N_EMBD) // 6144

// ---------------------------------------------------------------------------
// Scratch (no cudaMalloc allowed -> static __device__ globals)
// ---------------------------------------------------------------------------
__device__ float g_qkv[(size_t)MROWS * QKV_N];   // 100.7 MB
__device__ float g_y[(size_t)MROWS * N_EMBD];    //  33.6 MB
__device__ float g_cos[TT * (HD / 2)];
__device__ float g_sin[TT * (HD / 2)];
// fp16 operands (multi-purpose, reused across phases)
__device__ __half g_Ah[(size_t)MROWS * N_EMBD];   // x-hi / q-hi / y-hi
__device__ __half g_Al[(size_t)MROWS * N_EMBD];   // x-lo / q-lo / y-lo
__device__ __half g_B [(size_t)QKV_N * N_EMBD];   // w_attn^T / k / w_proj^T (single)
__device__ __half g_Vt[(size_t)MROWS * N_EMBD];   // V^T per head [bh][d][t] (single)

// ---------------------------------------------------------------------------
// Helpers (plain sm_103-legal PTX only: ldmatrix / mma.sync / cp.async)
// ---------------------------------------------------------------------------
__device__ __forceinline__ uint32_t smem_u32(const void* p) {
    uint32_t a;
    asm("{ .reg .u64 t; cvta.to.shared.u64 t, %1; cvt.u32.u64 %0, t; }"
        : "=r"(a) : "l"(p));
    return a;
}

__device__ __forceinline__ void ldsm_x4(uint32_t* r, uint32_t addr) {
    asm volatile("ldmatrix.sync.aligned.m8n8.x4.shared.b16 {%0,%1,%2,%3}, [%4];"
                 : "=r"(r[0]), "=r"(r[1]), "=r"(r[2]), "=r"(r[3]) : "r"(addr));
}

__device__ __forceinline__ void mma16816(float* c, const uint32_t* a,
                                         const uint32_t* b) {
    asm volatile(
        "mma.sync.aligned.m16n8k16.row.col.f32.f16.f16.f32 "
        "{%0,%1,%2,%3}, {%4,%5,%6,%7}, {%8,%9}, {%0,%1,%2,%3};"
        : "+f"(c[0]), "+f"(c[1]), "+f"(c[2]), "+f"(c[3])
        : "r"(a[0]), "r"(a[1]), "r"(a[2]), "r"(a[3]), "r"(b[0]), "r"(b[1]));
}

#define CP_ASYNC16(dst, src) \
    asm volatile("cp.async.cg.shared.global [%0], [%1], 16;" \
                 :: "r"(dst), "l"(src) : "memory")
#define CP_COMMIT() asm volatile("cp.async.commit_group;" ::: "memory")
#define CP_WAIT1()  asm volatile("cp.async.wait_group 1;" ::: "memory")

__device__ __forceinline__ void split2h(float x, __half& h, __half& l) {
    h = __float2half_rn(x);
    l = __float2half_rn(x - __half2float(h));
}

// pack two floats into fp16x2 hi + residual fp16x2 lo
__device__ __forceinline__ void pack_hl(float x, float y, uint32_t& h, uint32_t& l) {
    __half2 hh = __floats2half2_rn(x, y);
    float rx = x - __half2float(__low2half(hh));
    float ry = y - __half2float(__high2half(hh));
    __half2 ll = __floats2half2_rn(rx, ry);
    h = *(uint32_t*)&hh;
    l = *(uint32_t*)&ll;
}

// ---------------------------------------------------------------------------
// Convert kernels
// ---------------------------------------------------------------------------
// fp32 row-major -> fp16 hi/lo (same layout)
__global__ void conv_rm_kernel(const float* __restrict__ in,
                               __half* __restrict__ oh,
                               __half* __restrict__ ol, int n4) {
    int idx = blockIdx.x * blockDim.x + threadIdx.x;
    if (idx >= n4) return;
    float4 v = ((const float4*)in)[idx];
    __half2 h01 = __floats2half2_rn(v.x, v.y);
    __half2 h23 = __floats2half2_rn(v.z, v.w);
    __half2 l01 = __floats2half2_rn(v.x - __half2float(__low2half(h01)),
                                    v.y - __half2float(__high2half(h01)));
    __half2 l23 = __floats2half2_rn(v.z - __half2float(__low2half(h23)),
                                    v.w - __half2float(__high2half(h23)));
    ((__half2*)oh)[idx * 2]     = h01;
    ((__half2*)oh)[idx * 2 + 1] = h23;
    ((__half2*)ol)[idx * 2]     = l01;
    ((__half2*)ol)[idx * 2 + 1] = l23;
}

// B[K][N] fp32 row-major -> BT[N][K] single fp16
__global__ void conv_tr_kernel(const float* __restrict__ B,
                               __half* __restrict__ bt, int K, int N) {
    __shared__ float tile[32][33];
    int n0 = blockIdx.x * 32, k0 = blockIdx.y * 32;
    int tx = threadIdx.x, ty = threadIdx.y;
#pragma unroll
    for (int i = 0; i < 4; i++)
        tile[ty + i * 8][tx] = B[(size_t)(k0 + ty + i * 8) * N + n0 + tx];
    __syncthreads();
#pragma unroll
    for (int i = 0; i < 4; i++) {
        int n = ty + i * 8;
        bt[(size_t)(n0 + n) * K + k0 + tx] = __float2half_rn(tile[tx][n]);
    }
}

// q section of g_qkv: RoPE + split hi/lo fp16 [m][2048]
__global__ void conv_rope_q_kernel(const float* __restrict__ qkv,
                                   __half* __restrict__ oh,
                                   __half* __restrict__ ol) {
    int idx = blockIdx.x * blockDim.x + threadIdx.x;
    if (idx >= MROWS * 512) return;
    int m = idx >> 9;
    int col = (idx & 511) * 4;
    int t = m & (TT - 1);
    int i0 = (col & 127) >> 1;
    float4 v = *(const float4*)(qkv + (size_t)m * QKV_N + col);
    float c0 = g_cos[t * 64 + i0],     s0 = g_sin[t * 64 + i0];
    float c1 = g_cos[t * 64 + i0 + 1], s1 = g_sin[t * 64 + i0 + 1];
    float r0 = v.x * c0 - v.y * s0;
    float r1 = v.y * c0 + v.x * s0;
    float r2 = v.z * c1 - v.w * s1;
    float r3 = v.w * c1 + v.z * s1;
    __half2 h01 = __floats2half2_rn(r0, r1);
    __half2 h23 = __floats2half2_rn(r2, r3);
    __half2 l01 = __floats2half2_rn(r0 - __half2float(__low2half(h01)),
                                    r1 - __half2float(__high2half(h01)));
    __half2 l23 = __floats2half2_rn(r2 - __half2float(__low2half(h23)),
                                    r3 - __half2float(__high2half(h23)));
    size_t o = (size_t)m * N_EMBD + col;
    *(__half2*)(oh + o)     = h01;
    *(__half2*)(oh + o + 2) = h23;
    *(__half2*)(ol + o)     = l01;
    *(__half2*)(ol + o + 2) = l23;
}

// k section of g_qkv: RoPE + single fp16 [m][2048]
__global__ void conv_rope_k_kernel(const float* __restrict__ qkv,
                                   __half* __restrict__ ok) {
    int idx = blockIdx.x * blockDim.x + threadIdx.x;
    if (idx >= MROWS * 512) return;
    int m = idx >> 9;
    int col = (idx & 511) * 4;
    int t = m & (TT - 1);
    int i0 = (col & 127) >> 1;
    float4 v = *(const float4*)(qkv + (size_t)m * QKV_N + N_EMBD + col);
    float c0 = g_cos[t * 64 + i0],     s0 = g_sin[t * 64 + i0];
    float c1 = g_cos[t * 64 + i0 + 1], s1 = g_sin[t * 64 + i0 + 1];
    float r0 = v.x * c0 - v.y * s0;
    float r1 = v.y * c0 + v.x * s0;
    float r2 = v.z * c1 - v.w * s1;
    float r3 = v.w * c1 + v.z * s1;
    size_t o = (size_t)m * N_EMBD + col;
    *(__half2*)(ok + o)     = __floats2half2_rn(r0, r1);
    *(__half2*)(ok + o + 2) = __floats2half2_rn(r2, r3);
}

// V section of g_qkv -> per-head transposed single fp16: vt[(bh*128+d)*2048 + t]
__global__ void conv_vt_kernel(const float* __restrict__ qkv,
                               __half* __restrict__ vt) {
    __shared__ float tile[32][33];
    int bh = blockIdx.z;
    int b = bh >> 4, h = bh & 15;
    int t0 = blockIdx.x * 32, d0 = blockIdx.y * 32;
    int tx = threadIdx.x, ty = threadIdx.y;
#pragma unroll
    for (int i = 0; i < 4; i++)
        tile[ty + i * 8][tx] =
            qkv[(size_t)(b * TT + t0 + ty + i * 8) * QKV_N + 2 * N_EMBD + h * HD + d0 + tx];
    __syncthreads();
#pragma unroll
    for (int i = 0; i < 4; i++) {
        int d = ty + i * 8;
        vt[(size_t)(bh * HD + d0 + d) * TT + t0 + tx] = __float2half_rn(tile[tx][d]);
    }
}

// ---------------------------------------------------------------------------
// RoPE table
// ---------------------------------------------------------------------------
__global__ void rope_table_kernel() {
    int idx = blockIdx.x * blockDim.x + threadIdx.x;
    if (idx >= TT * 64) return;
    int t = idx >> 6;
    int i = idx & 63;
    double theta = pow(10000.0, -(double)i / 64.0);
    double ang = (double)t * theta;
    g_cos[idx] = (float)cos(ang);
    g_sin[idx] = (float)sin(ang);
}

// ---------------------------------------------------------------------------
// fp16 2-term GEMM via mma.sync: C = (Ah + Al) @ B^T, A split hi/lo fp16,
// B single fp16. CTA tile 128x256, BK=32, 8 warps, warp tile 64x64.
// ---------------------------------------------------------------------------
#define BM 128
#define BN 256
#define BK 32
#define PADB 80
#define A_BYTES (128 * PADB)                 // per A matrix (hi or lo)
#define B_BYTES (256 * PADB)
#define STG_BYTES (2 * A_BYTES + B_BYTES)    // 40960
#define GEMM_SMEM (2 * STG_BYTES)            // 81920

__global__ __launch_bounds__(256, 1) void gemm_mma_kernel(
    const __half* __restrict__ Ah, const __half* __restrict__ Al,
    const __half* __restrict__ B,
    float* __restrict__ C, int M, int N, int K)
{
    extern __shared__ char smc[];
    const uint32_t sbase = smem_u32(smc);
    const int tid = threadIdx.x;
    const int lane = tid & 31;
    const int wid = tid >> 5;
    const int wm = wid & 1;
    const int wn = wid >> 1;
    const int mBase = blockIdx.y * BM;
    const int nBase = blockIdx.x * BN;
    const int nch = K / BK;

    const int ldRow = tid >> 2;
    const int ldCh  = tid & 3;

    float acc[4][8][4];
#pragma unroll
    for (int i = 0; i < 4; i++)
#pragma unroll
        for (int j = 0; j < 8; j++)
#pragma unroll
            for (int r = 0; r < 4; r++) acc[i][j][r] = 0.0f;

    auto issue_stage = [&](int c, int buf) {
        const uint32_t st = sbase + buf * STG_BYTES;
        const int kOff = c * BK;
#pragma unroll
        for (int i = 0; i < 2; i++) {
            const int row = i * 64 + ldRow;
            const uint32_t so = row * PADB + ldCh * 16;
            CP_ASYNC16(st + so,
                       Ah + (size_t)(mBase + row) * K + kOff + ldCh * 8);
            CP_ASYNC16(st + A_BYTES + so,
                       Al + (size_t)(mBase + row) * K + kOff + ldCh * 8);
        }
#pragma unroll
        for (int i = 0; i < 4; i++) {
            const int row = i * 64 + ldRow;
            const uint32_t so = row * PADB + ldCh * 16;
            CP_ASYNC16(st + 2 * A_BYTES + so,
                       B + (size_t)(nBase + row) * K + kOff + ldCh * 8);
        }
    };

    issue_stage(0, 0);
    CP_COMMIT();

    const int arow = (lane & 7) + ((lane >> 3) & 1) * 8;
    const int akc8 = (lane >> 4) * 8;
    const int brow = (lane & 7) + ((lane >> 4) & 1) * 8;
    const int bkc8 = ((lane >> 3) & 1) * 8;

    for (int c = 0; c < nch; c++) {
        const int buf = c & 1;
        if (c + 1 < nch) issue_stage(c + 1, (c + 1) & 1);
        CP_COMMIT();
        CP_WAIT1();
        __syncthreads();

        const uint32_t st = sbase + buf * STG_BYTES;
        const uint32_t ahB = st;
        const uint32_t alB = st + A_BYTES;
        const uint32_t bB  = st + 2 * A_BYTES;

#pragma unroll
        for (int s = 0; s < 2; s++) {
            const int kofs = s * 16;
            uint32_t ah[4][4], al[4][4];
#pragma unroll
            for (int fm = 0; fm < 4; fm++) {
                const uint32_t off =
                    (uint32_t)((wm * 64 + fm * 16 + arow) * PADB +
                               (kofs + akc8) * 2);
                ldsm_x4(ah[fm], ahB + off);
                ldsm_x4(al[fm], alB + off);
            }
#pragma unroll
            for (int bi = 0; bi < 4; bi++) {
                uint32_t bf[4];
                const uint32_t off =
                    (uint32_t)((wn * 64 + bi * 16 + brow) * PADB +
                               (kofs + bkc8) * 2);
                ldsm_x4(bf, bB + off);
#pragma unroll
                for (int fm = 0; fm < 4; fm++) {
                    mma16816(acc[fm][2 * bi],     ah[fm], bf);
                    mma16816(acc[fm][2 * bi + 1], ah[fm], bf + 2);
                }
#pragma unroll
                for (int fm = 0; fm < 4; fm++) {
                    mma16816(acc[fm][2 * bi],     al[fm], bf);
                    mma16816(acc[fm][2 * bi + 1], al[fm], bf + 2);
                }
            }
        }
        __syncthreads();
    }

    const int r0 = lane >> 2;
    const int c0 = (lane & 3) * 2;
#pragma unroll
    for (int fm = 0; fm < 4; fm++) {
#pragma unroll
        for (int fn = 0; fn < 8; fn++) {
            const size_t row = (size_t)(mBase + wm * 64 + fm * 16 + r0);
            const int col = nBase + wn * 64 + fn * 8 + c0;
            *(float2*)(C + row * N + col) =
                make_float2(acc[fm][fn][0], acc[fm][fn][1]);
            *(float2*)(C + (row + 8) * N + col) =
                make_float2(acc[fm][fn][2], acc[fm][fn][3]);
        }
    }
}

// ---------------------------------------------------------------------------
// Flash attention: fp16 2-term. S = (Qh+Ql)@K^T (K single), online softmax,
// O += (Ph+Pl)@V (V single). CTA 256 thr / 8 warps, 128 q-rows x 64 keys.
// ---------------------------------------------------------------------------
#define FQ_BYTES   (128 * 272)               // per Q matrix (hi or lo)
#define FK_BYTES   (64 * 272)                // K single
#define FV_BYTES   (128 * 144)               // Vt single
#define FSTAGE     (FK_BYTES + FV_BYTES)     // 35840
#define FQ_TOTAL   (2 * FQ_BYTES)            // 69632
#define FA_SMEM    (FQ_TOTAL + 2 * FSTAGE)   // 141312

__global__ __launch_bounds__(256, 1) void flash_mma_kernel(
    const __half* __restrict__ qh, const __half* __restrict__ ql,
    const __half* __restrict__ kh, const __half* __restrict__ vt,
    float* __restrict__ y)
{
    extern __shared__ char smc[];
    const uint32_t sbase = smem_u32(smc);
    const int tid = threadIdx.x;
    const int lane = tid & 31;
    const int wid = tid >> 5;
    const int b = blockIdx.z, h = blockIdx.y;
    const int bh = b * NH + h;
    const int q0 = blockIdx.x * 128;
    const size_t bT = (size_t)b * TT;
    const int hoff = h * HD;

    {
#pragma unroll
        for (int i = 0; i < 8; i++) {
            int cid = i * 256 + tid;
            int row = cid >> 4, ch = cid & 15;
            const __half* sq = qh + (bT + q0 + row) * N_EMBD + hoff + ch * 8;
            const __half* sl = ql + (bT + q0 + row) * N_EMBD + hoff + ch * 8;
            CP_ASYNC16(sbase + row * 272 + ch * 16, sq);
            CP_ASYNC16(sbase + FQ_BYTES + row * 272 + ch * 16, sl);
        }
        CP_COMMIT();
    }

    auto issue_stage = [&](int it, int buf) {
        const uint32_t st = sbase + FQ_TOTAL + buf * FSTAGE;
        const int n0 = it * 64;
#pragma unroll
        for (int i = 0; i < 4; i++) {
            int cid = i * 256 + tid;
            int row = cid >> 4, ch = cid & 15;
            CP_ASYNC16(st + row * 272 + ch * 16,
                       kh + (bT + n0 + row) * N_EMBD + hoff + ch * 8);
        }
#pragma unroll
        for (int i = 0; i < 4; i++) {
            int cid = i * 256 + tid;
            int row = cid >> 3, ch = cid & 7;
            CP_ASYNC16(st + FK_BYTES + row * 144 + ch * 16,
                       vt + (size_t)(bh * HD + row) * TT + n0 + ch * 8);
        }
    };

    issue_stage(0, 0);
    CP_COMMIT();

    const int arow = (lane & 7) + ((lane >> 3) & 1) * 8;
    const int aoff = (lane >> 4) * 16;
    const int brow = (lane & 7) + ((lane >> 4) & 1) * 8;
    const int boff = ((lane >> 3) & 1) * 16;
    const int g = lane >> 2;
    const int tq = lane & 3;

    float O[16][4];
#pragma unroll
    for (int i = 0; i < 16; i++)
#pragma unroll
        for (int r = 0; r < 4; r++) O[i][r] = 0.0f;
    float ma = -INFINITY, mb = -INFINITY, la = 0.0f, lb = 0.0f;
    const float sc = 0.08838834764831845f;

    const int niter = TT / 64;
    for (int c = 0; c < niter; c++) {
        const int buf = c & 1;
        if (c + 1 < niter) issue_stage(c + 1, (c + 1) & 1);
        CP_COMMIT();
        CP_WAIT1();
        __syncthreads();

        const uint32_t kb = sbase + FQ_TOTAL + buf * FSTAGE;

        float s[8][4];
#pragma unroll
        for (int j = 0; j < 8; j++)
#pragma unroll
            for (int r = 0; r < 4; r++) s[j][r] = 0.0f;

#pragma unroll
        for (int kk = 0; kk < 8; kk++) {
            uint32_t qf[4], qlf[4];
            const uint32_t qo = (wid * 16 + arow) * 272 + kk * 32 + aoff;
            ldsm_x4(qf, sbase + qo);
            ldsm_x4(qlf, sbase + FQ_BYTES + qo);
#pragma unroll
            for (int bp = 0; bp < 2; bp++) {
                uint32_t khf[2][4];
#pragma unroll
                for (int u = 0; u < 2; u++) {
                    const int bi = 2 * bp + u;
                    const uint32_t ko = (bi * 16 + brow) * 272 + kk * 32 + boff;
                    ldsm_x4(khf[u], kb + ko);
                }
#pragma unroll
                for (int u = 0; u < 2; u++) {
                    const int bi = 2 * bp + u;
                    mma16816(s[2 * bi],     qf, khf[u]);
                    mma16816(s[2 * bi + 1], qf, khf[u] + 2);
                }
#pragma unroll
                for (int u = 0; u < 2; u++) {
                    const int bi = 2 * bp + u;
                    mma16816(s[2 * bi],     qlf, khf[u]);
                    mma16816(s[2 * bi + 1], qlf, khf[u] + 2);
                }
            }
        }

        float mxa = -INFINITY, mxb = -INFINITY;
#pragma unroll
        for (int j = 0; j < 8; j++) {
            s[j][0] *= sc; s[j][1] *= sc; s[j][2] *= sc; s[j][3] *= sc;
            mxa = fmaxf(mxa, fmaxf(s[j][0], s[j][1]));
            mxb = fmaxf(mxb, fmaxf(s[j][2], s[j][3]));
        }
        mxa = fmaxf(mxa, __shfl_xor_sync(0xffffffffu, mxa, 1));
        mxa = fmaxf(mxa, __shfl_xor_sync(0xffffffffu, mxa, 2));
        mxb = fmaxf(mxb, __shfl_xor_sync(0xffffffffu, mxb, 1));
        mxb = fmaxf(mxb, __shfl_xor_sync(0xffffffffu, mxb, 2));
        float mna = fmaxf(ma, mxa), mnb = fmaxf(mb, mxb);
        float alpha = __expf(ma - mna), beta = __expf(mb - mnb);
        ma = mna; mb = mnb;
        float sua = 0.0f, sub = 0.0f;
#pragma unroll
        for (int j = 0; j < 8; j++) {
            s[j][0] = __expf(s[j][0] - mna);
            s[j][1] = __expf(s[j][1] - mna);
            s[j][2] = __expf(s[j][2] - mnb);
            s[j][3] = __expf(s[j][3] - mnb);
            sua += s[j][0] + s[j][1];
            sub += s[j][2] + s[j][3];
        }
        sua += __shfl_xor_sync(0xffffffffu, sua, 1);
        sua += __shfl_xor_sync(0xffffffffu, sua, 2);
        sub += __shfl_xor_sync(0xffffffffu, sub, 1);
        sub += __shfl_xor_sync(0xffffffffu, sub, 2);
        la = la * alpha + sua;
        lb = lb * beta + sub;
#pragma unroll
        for (int j2 = 0; j2 < 16; j2++) {
            O[j2][0] *= alpha; O[j2][1] *= alpha;
            O[j2][2] *= beta;  O[j2][3] *= beta;
        }

        uint32_t Ph[4][4], Pl[4][4];
#pragma unroll
        for (int kp = 0; kp < 4; kp++) {
            pack_hl(s[2 * kp][0],     s[2 * kp][1],     Ph[kp][0], Pl[kp][0]);
            pack_hl(s[2 * kp][2],     s[2 * kp][3],     Ph[kp][1], Pl[kp][1]);
            pack_hl(s[2 * kp + 1][0], s[2 * kp + 1][1], Ph[kp][2], Pl[kp][2]);
            pack_hl(s[2 * kp + 1][2], s[2 * kp + 1][3], Ph[kp][3], Pl[kp][3]);
        }

        const uint32_t vb = kb + FK_BYTES;
#pragma unroll
        for (int kp = 0; kp < 4; kp++) {
#pragma unroll
            for (int jp = 0; jp < 4; jp++) {
                uint32_t vhf[2][4];
#pragma unroll
                for (int u = 0; u < 2; u++) {
                    const int j4 = 2 * jp + u;
                    const uint32_t vo = (j4 * 16 + brow) * 144 + kp * 32 + boff;
                    ldsm_x4(vhf[u], vb + vo);
                }
#pragma unroll
                for (int u = 0; u < 2; u++) {
                    const int j4 = 2 * jp + u;
                    mma16816(O[2 * j4],     Ph[kp], vhf[u]);
                    mma16816(O[2 * j4 + 1], Ph[kp], vhf[u] + 2);
                }
#pragma unroll
                for (int u = 0; u < 2; u++) {
                    const int j4 = 2 * jp + u;
                    mma16816(O[2 * j4],     Pl[kp], vhf[u]);
                    mma16816(O[2 * j4 + 1], Pl[kp], vhf[u] + 2);
                }
            }
        }
        __syncthreads();
    }

    const float inva = 1.0f / la, invb = 1.0f / lb;
    const size_t rowa = bT + q0 + wid * 16 + g;
    const size_t rowb = rowa + 8;
#pragma unroll
    for (int j2 = 0; j2 < 16; j2++) {
        const int col = hoff + j2 * 8 + tq * 2;
        *(float2*)(y + rowa * N_EMBD + col) =
            make_float2(O[j2][0] * inva, O[j2][1] * inva);
        *(float2*)(y + rowb * N_EMBD + col) =
            make_float2(O[j2][2] * invb, O[j2][3] * invb);
    }
}

// ---------------------------------------------------------------------------
// Launch
// ---------------------------------------------------------------------------
extern "C" void kernel_launch(void* const* d_in, const int* in_sizes, int n_in,
                              void* d_out, int out_size)
{
    const float* x      = (const float*)d_in[0];
    const float* w_attn = (const float*)d_in[1];
    const float* w_proj = (const float*)d_in[2];
    float* out = (float*)d_out;

    float *qkv = nullptr, *y = nullptr;
    __half *Ah, *Al, *Bm, *Vt;
    cudaGetSymbolAddress((void**)&qkv, g_qkv);
    cudaGetSymbolAddress((void**)&y, g_y);
    cudaGetSymbolAddress((void**)&Ah, g_Ah);
    cudaGetSymbolAddress((void**)&Al, g_Al);
    cudaGetSymbolAddress((void**)&Bm, g_B);
    cudaGetSymbolAddress((void**)&Vt, g_Vt);

    cudaFuncSetAttribute(gemm_mma_kernel,
                         cudaFuncAttributeMaxDynamicSharedMemorySize, GEMM_SMEM);
    cudaFuncSetAttribute(flash_mma_kernel,
                         cudaFuncAttributeMaxDynamicSharedMemorySize, FA_SMEM);

    const int n4 = MROWS * N_EMBD / 4;

    // 1. RoPE table
    rope_table_kernel<<<(TT * 64 + 255) / 256, 256>>>();

    // 2. Convert x (split hi/lo) and w_attn^T (single)
    conv_rm_kernel<<<(n4 + 255) / 256, 256>>>(x, Ah, Al, n4);
    conv_tr_kernel<<<dim3(QKV_N / 32, N_EMBD / 32), dim3(32, 8)>>>(
        w_attn, Bm, N_EMBD, QKV_N);

    // 3. QKV projection (fp16 2-term)
    gemm_mma_kernel<<<dim3(QKV_N / BN, MROWS / BM), 256, GEMM_SMEM>>>(
        Ah, Al, Bm, qkv, MROWS, QKV_N, N_EMBD);

    // 4. RoPE + convert: q split -> Ah/Al, k single -> Bm, v^T single -> Vt
    conv_rope_q_kernel<<<(MROWS * 512 + 255) / 256, 256>>>(qkv, Ah, Al);
    conv_rope_k_kernel<<<(MROWS * 512 + 255) / 256, 256>>>(qkv, Bm);
    conv_vt_kernel<<<dim3(TT / 32, HD / 32, BB * NH), dim3(32, 8)>>>(qkv, Vt);

    // 5. Flash attention (fp16 2-term) -> g_y
    flash_mma_kernel<<<dim3(TT / 128, NH, BB), 256, FA_SMEM>>>(
        Ah, Al, Bm, Vt, y);

    // 6. Convert y (split) and w_proj^T (single)
    conv_rm_kernel<<<(n4 + 255) / 256, 256>>>(y, Ah, Al, n4);
    conv_tr_kernel<<<dim3(N_EMBD / 32, N_EMBD / 32), dim3(32, 8)>>>(
        w_proj, Bm, N_EMBD, N_EMBD);

    // 7. Output projection (fp16 2-term)
    gemm_mma_kernel<<<dim3(N_EMBD / BN, MROWS / BM), 256, GEMM_SMEM>>>(
        Ah, Al, Bm, out, MROWS, N_EMBD, N_EMBD);
}

// round 11
// speedup vs baseline: 1.4843x; 1.0262x over previous
#include <cuda_runtime.h>
#include <cuda_fp16.h>
#include <stdint.h>
#include <math.h>

// ---------------------------------------------------------------------------
// Problem constants
// ---------------------------------------------------------------------------
#define N_EMBD 2048
#define NH     16
#define HD     128
#define TT     2048         // seq len
#define BB     2            // batch
#define MROWS  (BB * TT)    // 4096 flattened (b, t) rows
#define QKV_N  (3 * N_EMBD) // 6144

// ---------------------------------------------------------------------------
// Scratch (no cudaMalloc allowed -> static __device__ globals)
// ---------------------------------------------------------------------------
__device__ float g_cos[TT * (HD / 2)];
__device__ float g_sin[TT * (HD / 2)];
__device__ __half g_Ah[(size_t)MROWS * N_EMBD];   // x-hi, later y-hi
__device__ __half g_Al[(size_t)MROWS * N_EMBD];   // x-lo, later y-lo
__device__ __half g_Wa[(size_t)QKV_N * N_EMBD];   // w_attn^T [N][K]
__device__ __half g_Wp[(size_t)N_EMBD * N_EMBD];  // w_proj^T [N][K]
__device__ __half g_Qh[(size_t)MROWS * N_EMBD];   // roped q hi
__device__ __half g_Ql[(size_t)MROWS * N_EMBD];   // roped q lo
__device__ __half g_K [(size_t)MROWS * N_EMBD];   // roped k (single)
__device__ __half g_Vh[(size_t)MROWS * N_EMBD];   // v row-major (single)
__device__ __half g_Vt[(size_t)MROWS * N_EMBD];   // V^T per head [bh][d][t]

// ---------------------------------------------------------------------------
// Helpers (plain sm_103-legal PTX only: ldmatrix / mma.sync / cp.async)
// ---------------------------------------------------------------------------
__device__ __forceinline__ uint32_t smem_u32(const void* p) {
    uint32_t a;
    asm("{ .reg .u64 t; cvta.to.shared.u64 t, %1; cvt.u32.u64 %0, t; }"
        : "=r"(a) : "l"(p));
    return a;
}

__device__ __forceinline__ void ldsm_x4(uint32_t* r, uint32_t addr) {
    asm volatile("ldmatrix.sync.aligned.m8n8.x4.shared.b16 {%0,%1,%2,%3}, [%4];"
                 : "=r"(r[0]), "=r"(r[1]), "=r"(r[2]), "=r"(r[3]) : "r"(addr));
}

__device__ __forceinline__ void mma16816(float* c, const uint32_t* a,
                                         const uint32_t* b) {
    asm volatile(
        "mma.sync.aligned.m16n8k16.row.col.f32.f16.f16.f32 "
        "{%0,%1,%2,%3}, {%4,%5,%6,%7}, {%8,%9}, {%0,%1,%2,%3};"
        : "+f"(c[0]), "+f"(c[1]), "+f"(c[2]), "+f"(c[3])
        : "r"(a[0]), "r"(a[1]), "r"(a[2]), "r"(a[3]), "r"(b[0]), "r"(b[1]));
}

#define CP_ASYNC16(dst, src) \
    asm volatile("cp.async.cg.shared.global [%0], [%1], 16;" \
                 :: "r"(dst), "l"(src) : "memory")
#define CP_COMMIT() asm volatile("cp.async.commit_group;" ::: "memory")
#define CP_WAIT1()  asm volatile("cp.async.wait_group 1;" ::: "memory")

// pack two floats into fp16x2 hi + residual fp16x2 lo
__device__ __forceinline__ void pack_hl(float x, float y, uint32_t& h, uint32_t& l) {
    __half2 hh = __floats2half2_rn(x, y);
    float rx = x - __half2float(__low2half(hh));
    float ry = y - __half2float(__high2half(hh));
    __half2 ll = __floats2half2_rn(rx, ry);
    h = *(uint32_t*)&hh;
    l = *(uint32_t*)&ll;
}

// ---------------------------------------------------------------------------
// Convert kernels
// ---------------------------------------------------------------------------
// fp32 row-major -> fp16 hi/lo (same layout)
__global__ void conv_rm_kernel(const float* __restrict__ in,
                               __half* __restrict__ oh,
                               __half* __restrict__ ol, int n4) {
    int idx = blockIdx.x * blockDim.x + threadIdx.x;
    if (idx >= n4) return;
    float4 v = ((const float4*)in)[idx];
    __half2 h01 = __floats2half2_rn(v.x, v.y);
    __half2 h23 = __floats2half2_rn(v.z, v.w);
    __half2 l01 = __floats2half2_rn(v.x - __half2float(__low2half(h01)),
                                    v.y - __half2float(__high2half(h01)));
    __half2 l23 = __floats2half2_rn(v.z - __half2float(__low2half(h23)),
                                    v.w - __half2float(__high2half(h23)));
    ((__half2*)oh)[idx * 2]     = h01;
    ((__half2*)oh)[idx * 2 + 1] = h23;
    ((__half2*)ol)[idx * 2]     = l01;
    ((__half2*)ol)[idx * 2 + 1] = l23;
}

// B[K][N] fp32 row-major -> BT[N][K] single fp16
__global__ void conv_tr_kernel(const float* __restrict__ B,
                               __half* __restrict__ bt, int K, int N) {
    __shared__ float tile[32][33];
    int n0 = blockIdx.x * 32, k0 = blockIdx.y * 32;
    int tx = threadIdx.x, ty = threadIdx.y;
#pragma unroll
    for (int i = 0; i < 4; i++)
        tile[ty + i * 8][tx] = B[(size_t)(k0 + ty + i * 8) * N + n0 + tx];
    __syncthreads();
#pragma unroll
    for (int i = 0; i < 4; i++) {
        int n = ty + i * 8;
        bt[(size_t)(n0 + n) * K + k0 + tx] = __float2half_rn(tile[tx][n]);
    }
}

// Vh [m][h*128+d] fp16 -> Vt [(bh*128+d)][t] fp16
__global__ void conv_vth_kernel(const __half* __restrict__ vh,
                                __half* __restrict__ vt) {
    __shared__ __half tile[32][34];
    int bh = blockIdx.z;
    int b = bh >> 4, h = bh & 15;
    int t0 = blockIdx.x * 32, d0 = blockIdx.y * 32;
    int tx = threadIdx.x, ty = threadIdx.y;
#pragma unroll
    for (int i = 0; i < 4; i++)
        tile[ty + i * 8][tx] =
            vh[(size_t)(b * TT + t0 + ty + i * 8) * N_EMBD + h * HD + d0 + tx];
    __syncthreads();
#pragma unroll
    for (int i = 0; i < 4; i++) {
        int d = ty + i * 8;
        vt[(size_t)(bh * HD + d0 + d) * TT + t0 + tx] = tile[tx][d];
    }
}

// ---------------------------------------------------------------------------
// RoPE table
// ---------------------------------------------------------------------------
__global__ void rope_table_kernel() {
    int idx = blockIdx.x * blockDim.x + threadIdx.x;
    if (idx >= TT * 64) return;
    int t = idx >> 6;
    int i = idx & 63;
    double theta = pow(10000.0, -(double)i / 64.0);
    double ang = (double)t * theta;
    g_cos[idx] = (float)cos(ang);
    g_sin[idx] = (float)sin(ang);
}

// ---------------------------------------------------------------------------
// Shared GEMM tile config (128x256, BK=32, 8 warps, warp tile 64x64)
// ---------------------------------------------------------------------------
#define BM 128
#define BN 256
#define BK 32
#define PADB 80
#define A_BYTES (128 * PADB)
#define B_BYTES (256 * PADB)
#define STG_BYTES (2 * A_BYTES + B_BYTES)    // 40960
#define GEMM_SMEM (2 * STG_BYTES)            // 81920

// Mainloop macro-free shared body implemented in each kernel (epilogues differ).

// ---------------------------------------------------------------------------
// QKV GEMM: C = (Ah+Al) @ Wa^T, fused epilogue:
//   q section -> RoPE + hi/lo split -> Qh/Ql
//   k section -> RoPE + single fp16 -> K
//   v section -> single fp16 -> Vh
// ---------------------------------------------------------------------------
__global__ __launch_bounds__(256, 1) void gemm_qkv_kernel(
    const __half* __restrict__ Ah, const __half* __restrict__ Al,
    const __half* __restrict__ B,
    __half* __restrict__ Qh, __half* __restrict__ Ql,
    __half* __restrict__ Kb, __half* __restrict__ Vh)
{
    const int M = MROWS, N = QKV_N, K = N_EMBD;
    extern __shared__ char smc[];
    const uint32_t sbase = smem_u32(smc);
    const int tid = threadIdx.x;
    const int lane = tid & 31;
    const int wid = tid >> 5;
    const int wm = wid & 1;
    const int wn = wid >> 1;
    const int mBase = blockIdx.y * BM;
    const int nBase = blockIdx.x * BN;
    const int nch = K / BK;

    const int ldRow = tid >> 2;
    const int ldCh  = tid & 3;

    float acc[4][8][4];
#pragma unroll
    for (int i = 0; i < 4; i++)
#pragma unroll
        for (int j = 0; j < 8; j++)
#pragma unroll
            for (int r = 0; r < 4; r++) acc[i][j][r] = 0.0f;

    auto issue_stage = [&](int c, int buf) {
        const uint32_t st = sbase + buf * STG_BYTES;
        const int kOff = c * BK;
#pragma unroll
        for (int i = 0; i < 2; i++) {
            const int row = i * 64 + ldRow;
            const uint32_t so = row * PADB + ldCh * 16;
            CP_ASYNC16(st + so,
                       Ah + (size_t)(mBase + row) * K + kOff + ldCh * 8);
            CP_ASYNC16(st + A_BYTES + so,
                       Al + (size_t)(mBase + row) * K + kOff + ldCh * 8);
        }
#pragma unroll
        for (int i = 0; i < 4; i++) {
            const int row = i * 64 + ldRow;
            const uint32_t so = row * PADB + ldCh * 16;
            CP_ASYNC16(st + 2 * A_BYTES + so,
                       B + (size_t)(nBase + row) * K + kOff + ldCh * 8);
        }
    };

    issue_stage(0, 0);
    CP_COMMIT();

    const int arow = (lane & 7) + ((lane >> 3) & 1) * 8;
    const int akc8 = (lane >> 4) * 8;
    const int brow = (lane & 7) + ((lane >> 4) & 1) * 8;
    const int bkc8 = ((lane >> 3) & 1) * 8;

    for (int c = 0; c < nch; c++) {
        const int buf = c & 1;
        if (c + 1 < nch) issue_stage(c + 1, (c + 1) & 1);
        CP_COMMIT();
        CP_WAIT1();
        __syncthreads();

        const uint32_t st = sbase + buf * STG_BYTES;
        const uint32_t ahB = st;
        const uint32_t alB = st + A_BYTES;
        const uint32_t bB  = st + 2 * A_BYTES;

#pragma unroll
        for (int s = 0; s < 2; s++) {
            const int kofs = s * 16;
            uint32_t ah[4][4], al[4][4];
#pragma unroll
            for (int fm = 0; fm < 4; fm++) {
                const uint32_t off =
                    (uint32_t)((wm * 64 + fm * 16 + arow) * PADB +
                               (kofs + akc8) * 2);
                ldsm_x4(ah[fm], ahB + off);
                ldsm_x4(al[fm], alB + off);
            }
#pragma unroll
            for (int bi = 0; bi < 4; bi++) {
                uint32_t bf[4];
                const uint32_t off =
                    (uint32_t)((wn * 64 + bi * 16 + brow) * PADB +
                               (kofs + bkc8) * 2);
                ldsm_x4(bf, bB + off);
#pragma unroll
                for (int fm = 0; fm < 4; fm++) {
                    mma16816(acc[fm][2 * bi],     ah[fm], bf);
                    mma16816(acc[fm][2 * bi + 1], ah[fm], bf + 2);
                }
#pragma unroll
                for (int fm = 0; fm < 4; fm++) {
                    mma16816(acc[fm][2 * bi],     al[fm], bf);
                    mma16816(acc[fm][2 * bi + 1], al[fm], bf + 2);
                }
            }
        }
        __syncthreads();
    }

    // ---- fused epilogue ----
    const int r0 = lane >> 2;
    const int c0 = (lane & 3) * 2;
    const int sec = nBase >> 11;          // 0=q, 1=k, 2=v (CTA-uniform)
    const int nLoc = nBase & (N_EMBD - 1);

#pragma unroll
    for (int fm = 0; fm < 4; fm++) {
        const int row = mBase + wm * 64 + fm * 16 + r0;
        const int t0 = row & (TT - 1);
        const int t1 = (row + 8) & (TT - 1);
#pragma unroll
        for (int fn = 0; fn < 8; fn++) {
            const int col = nLoc + wn * 64 + fn * 8 + c0;
            float v0 = acc[fm][fn][0], v1 = acc[fm][fn][1];
            float v2 = acc[fm][fn][2], v3 = acc[fm][fn][3];
            if (sec < 2) {
                const int i0 = (col & 127) >> 1;
                float cA = g_cos[t0 * 64 + i0], sA = g_sin[t0 * 64 + i0];
                float cB = g_cos[t1 * 64 + i0], sB = g_sin[t1 * 64 + i0];
                float r00 = v0 * cA - v1 * sA, r01 = v1 * cA + v0 * sA;
                float r10 = v2 * cB - v3 * sB, r11 = v3 * cB + v2 * sB;
                if (sec == 0) {
                    uint32_t h0, l0, h1, l1;
                    pack_hl(r00, r01, h0, l0);
                    pack_hl(r10, r11, h1, l1);
                    *(uint32_t*)(Qh + (size_t)row * N_EMBD + col) = h0;
                    *(uint32_t*)(Ql + (size_t)row * N_EMBD + col) = l0;
                    *(uint32_t*)(Qh + (size_t)(row + 8) * N_EMBD + col) = h1;
                    *(uint32_t*)(Ql + (size_t)(row + 8) * N_EMBD + col) = l1;
                } else {
                    *(__half2*)(Kb + (size_t)row * N_EMBD + col) =
                        __floats2half2_rn(r00, r01);
                    *(__half2*)(Kb + (size_t)(row + 8) * N_EMBD + col) =
                        __floats2half2_rn(r10, r11);
                }
            } else {
                *(__half2*)(Vh + (size_t)row * N_EMBD + col) =
                    __floats2half2_rn(v0, v1);
                *(__half2*)(Vh + (size_t)(row + 8) * N_EMBD + col) =
                    __floats2half2_rn(v2, v3);
            }
        }
    }
}

// ---------------------------------------------------------------------------
// Proj GEMM: C(fp32) = (Ah+Al) @ B^T  (plain epilogue)
// ---------------------------------------------------------------------------
__global__ __launch_bounds__(256, 1) void gemm_mma_kernel(
    const __half* __restrict__ Ah, const __half* __restrict__ Al,
    const __half* __restrict__ B,
    float* __restrict__ C, int M, int N, int K)
{
    extern __shared__ char smc[];
    const uint32_t sbase = smem_u32(smc);
    const int tid = threadIdx.x;
    const int lane = tid & 31;
    const int wid = tid >> 5;
    const int wm = wid & 1;
    const int wn = wid >> 1;
    const int mBase = blockIdx.y * BM;
    const int nBase = blockIdx.x * BN;
    const int nch = K / BK;

    const int ldRow = tid >> 2;
    const int ldCh  = tid & 3;

    float acc[4][8][4];
#pragma unroll
    for (int i = 0; i < 4; i++)
#pragma unroll
        for (int j = 0; j < 8; j++)
#pragma unroll
            for (int r = 0; r < 4; r++) acc[i][j][r] = 0.0f;

    auto issue_stage = [&](int c, int buf) {
        const uint32_t st = sbase + buf * STG_BYTES;
        const int kOff = c * BK;
#pragma unroll
        for (int i = 0; i < 2; i++) {
            const int row = i * 64 + ldRow;
            const uint32_t so = row * PADB + ldCh * 16;
            CP_ASYNC16(st + so,
                       Ah + (size_t)(mBase + row) * K + kOff + ldCh * 8);
            CP_ASYNC16(st + A_BYTES + so,
                       Al + (size_t)(mBase + row) * K + kOff + ldCh * 8);
        }
#pragma unroll
        for (int i = 0; i < 4; i++) {
            const int row = i * 64 + ldRow;
            const uint32_t so = row * PADB + ldCh * 16;
            CP_ASYNC16(st + 2 * A_BYTES + so,
                       B + (size_t)(nBase + row) * K + kOff + ldCh * 8);
        }
    };

    issue_stage(0, 0);
    CP_COMMIT();

    const int arow = (lane & 7) + ((lane >> 3) & 1) * 8;
    const int akc8 = (lane >> 4) * 8;
    const int brow = (lane & 7) + ((lane >> 4) & 1) * 8;
    const int bkc8 = ((lane >> 3) & 1) * 8;

    for (int c = 0; c < nch; c++) {
        const int buf = c & 1;
        if (c + 1 < nch) issue_stage(c + 1, (c + 1) & 1);
        CP_COMMIT();
        CP_WAIT1();
        __syncthreads();

        const uint32_t st = sbase + buf * STG_BYTES;
        const uint32_t ahB = st;
        const uint32_t alB = st + A_BYTES;
        const uint32_t bB  = st + 2 * A_BYTES;

#pragma unroll
        for (int s = 0; s < 2; s++) {
            const int kofs = s * 16;
            uint32_t ah[4][4], al[4][4];
#pragma unroll
            for (int fm = 0; fm < 4; fm++) {
                const uint32_t off =
                    (uint32_t)((wm * 64 + fm * 16 + arow) * PADB +
                               (kofs + akc8) * 2);
                ldsm_x4(ah[fm], ahB + off);
                ldsm_x4(al[fm], alB + off);
            }
#pragma unroll
            for (int bi = 0; bi < 4; bi++) {
                uint32_t bf[4];
                const uint32_t off =
                    (uint32_t)((wn * 64 + bi * 16 + brow) * PADB +
                               (kofs + bkc8) * 2);
                ldsm_x4(bf, bB + off);
#pragma unroll
                for (int fm = 0; fm < 4; fm++) {
                    mma16816(acc[fm][2 * bi],     ah[fm], bf);
                    mma16816(acc[fm][2 * bi + 1], ah[fm], bf + 2);
                }
#pragma unroll
                for (int fm = 0; fm < 4; fm++) {
                    mma16816(acc[fm][2 * bi],     al[fm], bf);
                    mma16816(acc[fm][2 * bi + 1], al[fm], bf + 2);
                }
            }
        }
        __syncthreads();
    }

    const int r0 = lane >> 2;
    const int c0 = (lane & 3) * 2;
#pragma unroll
    for (int fm = 0; fm < 4; fm++) {
#pragma unroll
        for (int fn = 0; fn < 8; fn++) {
            const size_t row = (size_t)(mBase + wm * 64 + fm * 16 + r0);
            const int col = nBase + wn * 64 + fn * 8 + c0;
            *(float2*)(C + row * N + col) =
                make_float2(acc[fm][fn][0], acc[fm][fn][1]);
            *(float2*)(C + (row + 8) * N + col) =
                make_float2(acc[fm][fn][2], acc[fm][fn][3]);
        }
    }
}

// ---------------------------------------------------------------------------
// Flash attention: fp16 2-term, epilogue writes split fp16 O into Ah/Al.
// ---------------------------------------------------------------------------
#define FQ_BYTES   (128 * 272)
#define FK_BYTES   (64 * 272)
#define FV_BYTES   (128 * 144)
#define FSTAGE     (FK_BYTES + FV_BYTES)
#define FQ_TOTAL   (2 * FQ_BYTES)
#define FA_SMEM    (FQ_TOTAL + 2 * FSTAGE)

__global__ __launch_bounds__(256, 1) void flash_mma_kernel(
    const __half* __restrict__ qh, const __half* __restrict__ ql,
    const __half* __restrict__ kh, const __half* __restrict__ vt,
    __half* __restrict__ yh, __half* __restrict__ yl)
{
    extern __shared__ char smc[];
    const uint32_t sbase = smem_u32(smc);
    const int tid = threadIdx.x;
    const int lane = tid & 31;
    const int wid = tid >> 5;
    const int b = blockIdx.z, h = blockIdx.y;
    const int bh = b * NH + h;
    const int q0 = blockIdx.x * 128;
    const size_t bT = (size_t)b * TT;
    const int hoff = h * HD;

    {
#pragma unroll
        for (int i = 0; i < 8; i++) {
            int cid = i * 256 + tid;
            int row = cid >> 4, ch = cid & 15;
            CP_ASYNC16(sbase + row * 272 + ch * 16,
                       qh + (bT + q0 + row) * N_EMBD + hoff + ch * 8);
            CP_ASYNC16(sbase + FQ_BYTES + row * 272 + ch * 16,
                       ql + (bT + q0 + row) * N_EMBD + hoff + ch * 8);
        }
        CP_COMMIT();
    }

    auto issue_stage = [&](int it, int buf) {
        const uint32_t st = sbase + FQ_TOTAL + buf * FSTAGE;
        const int n0 = it * 64;
#pragma unroll
        for (int i = 0; i < 4; i++) {
            int cid = i * 256 + tid;
            int row = cid >> 4, ch = cid & 15;
            CP_ASYNC16(st + row * 272 + ch * 16,
                       kh + (bT + n0 + row) * N_EMBD + hoff + ch * 8);
        }
#pragma unroll
        for (int i = 0; i < 4; i++) {
            int cid = i * 256 + tid;
            int row = cid >> 3, ch = cid & 7;
            CP_ASYNC16(st + FK_BYTES + row * 144 + ch * 16,
                       vt + (size_t)(bh * HD + row) * TT + n0 + ch * 8);
        }
    };

    issue_stage(0, 0);
    CP_COMMIT();

    const int arow = (lane & 7) + ((lane >> 3) & 1) * 8;
    const int aoff = (lane >> 4) * 16;
    const int brow = (lane & 7) + ((lane >> 4) & 1) * 8;
    const int boff = ((lane >> 3) & 1) * 16;
    const int g = lane >> 2;
    const int tq = lane & 3;

    float O[16][4];
#pragma unroll
    for (int i = 0; i < 16; i++)
#pragma unroll
        for (int r = 0; r < 4; r++) O[i][r] = 0.0f;
    float ma = -INFINITY, mb = -INFINITY, la = 0.0f, lb = 0.0f;
    const float sc = 0.08838834764831845f;

    const int niter = TT / 64;
    for (int c = 0; c < niter; c++) {
        const int buf = c & 1;
        if (c + 1 < niter) issue_stage(c + 1, (c + 1) & 1);
        CP_COMMIT();
        CP_WAIT1();
        __syncthreads();

        const uint32_t kb = sbase + FQ_TOTAL + buf * FSTAGE;

        float s[8][4];
#pragma unroll
        for (int j = 0; j < 8; j++)
#pragma unroll
            for (int r = 0; r < 4; r++) s[j][r] = 0.0f;

#pragma unroll
        for (int kk = 0; kk < 8; kk++) {
            uint32_t qf[4], qlf[4];
            const uint32_t qo = (wid * 16 + arow) * 272 + kk * 32 + aoff;
            ldsm_x4(qf, sbase + qo);
            ldsm_x4(qlf, sbase + FQ_BYTES + qo);
#pragma unroll
            for (int bp = 0; bp < 2; bp++) {
                uint32_t khf[2][4];
#pragma unroll
                for (int u = 0; u < 2; u++) {
                    const int bi = 2 * bp + u;
                    const uint32_t ko = (bi * 16 + brow) * 272 + kk * 32 + boff;
                    ldsm_x4(khf[u], kb + ko);
                }
#pragma unroll
                for (int u = 0; u < 2; u++) {
                    const int bi = 2 * bp + u;
                    mma16816(s[2 * bi],     qf, khf[u]);
                    mma16816(s[2 * bi + 1], qf, khf[u] + 2);
                }
#pragma unroll
                for (int u = 0; u < 2; u++) {
                    const int bi = 2 * bp + u;
                    mma16816(s[2 * bi],     qlf, khf[u]);
                    mma16816(s[2 * bi + 1], qlf, khf[u] + 2);
                }
            }
        }

        float mxa = -INFINITY, mxb = -INFINITY;
#pragma unroll
        for (int j = 0; j < 8; j++) {
            s[j][0] *= sc; s[j][1] *= sc; s[j][2] *= sc; s[j][3] *= sc;
            mxa = fmaxf(mxa, fmaxf(s[j][0], s[j][1]));
            mxb = fmaxf(mxb, fmaxf(s[j][2], s[j][3]));
        }
        mxa = fmaxf(mxa, __shfl_xor_sync(0xffffffffu, mxa, 1));
        mxa = fmaxf(mxa, __shfl_xor_sync(0xffffffffu, mxa, 2));
        mxb = fmaxf(mxb, __shfl_xor_sync(0xffffffffu, mxb, 1));
        mxb = fmaxf(mxb, __shfl_xor_sync(0xffffffffu, mxb, 2));
        float mna = fmaxf(ma, mxa), mnb = fmaxf(mb, mxb);
        float alpha = __expf(ma - mna), beta = __expf(mb - mnb);
        ma = mna; mb = mnb;
        float sua = 0.0f, sub = 0.0f;
#pragma unroll
        for (int j = 0; j < 8; j++) {
            s[j][0] = __expf(s[j][0] - mna);
            s[j][1] = __expf(s[j][1] - mna);
            s[j][2] = __expf(s[j][2] - mnb);
            s[j][3] = __expf(s[j][3] - mnb);
            sua += s[j][0] + s[j][1];
            sub += s[j][2] + s[j][3];
        }
        sua += __shfl_xor_sync(0xffffffffu, sua, 1);
        sua += __shfl_xor_sync(0xffffffffu, sua, 2);
        sub += __shfl_xor_sync(0xffffffffu, sub, 1);
        sub += __shfl_xor_sync(0xffffffffu, sub, 2);
        la = la * alpha + sua;
        lb = lb * beta + sub;
#pragma unroll
        for (int j2 = 0; j2 < 16; j2++) {
            O[j2][0] *= alpha; O[j2][1] *= alpha;
            O[j2][2] *= beta;  O[j2][3] *= beta;
        }

        uint32_t Ph[4][4], Pl[4][4];
#pragma unroll
        for (int kp = 0; kp < 4; kp++) {
            pack_hl(s[2 * kp][0],     s[2 * kp][1],     Ph[kp][0], Pl[kp][0]);
            pack_hl(s[2 * kp][2],     s[2 * kp][3],     Ph[kp][1], Pl[kp][1]);
            pack_hl(s[2 * kp + 1][0], s[2 * kp + 1][1], Ph[kp][2], Pl[kp][2]);
            pack_hl(s[2 * kp + 1][2], s[2 * kp + 1][3], Ph[kp][3], Pl[kp][3]);
        }

        const uint32_t vb = kb + FK_BYTES;
#pragma unroll
        for (int kp = 0; kp < 4; kp++) {
#pragma unroll
            for (int jp = 0; jp < 4; jp++) {
                uint32_t vhf[2][4];
#pragma unroll
                for (int u = 0; u < 2; u++) {
                    const int j4 = 2 * jp + u;
                    const uint32_t vo = (j4 * 16 + brow) * 144 + kp * 32 + boff;
                    ldsm_x4(vhf[u], vb + vo);
                }
#pragma unroll
                for (int u = 0; u < 2; u++) {
                    const int j4 = 2 * jp + u;
                    mma16816(O[2 * j4],     Ph[kp], vhf[u]);
                    mma16816(O[2 * j4 + 1], Ph[kp], vhf[u] + 2);
                }
#pragma unroll
                for (int u = 0; u < 2; u++) {
                    const int j4 = 2 * jp + u;
                    mma16816(O[2 * j4],     Pl[kp], vhf[u]);
                    mma16816(O[2 * j4 + 1], Pl[kp], vhf[u] + 2);
                }
            }
        }
        __syncthreads();
    }

    // ---- epilogue: normalize + split to fp16 hi/lo, write into Ah/Al ----
    const float inva = 1.0f / la, invb = 1.0f / lb;
    const size_t rowa = bT + q0 + wid * 16 + g;
    const size_t rowb = rowa + 8;
#pragma unroll
    for (int j2 = 0; j2 < 16; j2++) {
        const int col = hoff + j2 * 8 + tq * 2;
        uint32_t h0, l0, h1, l1;
        pack_hl(O[j2][0] * inva, O[j2][1] * inva, h0, l0);
        pack_hl(O[j2][2] * invb, O[j2][3] * invb, h1, l1);
        *(uint32_t*)(yh + rowa * N_EMBD + col) = h0;
        *(uint32_t*)(yl + rowa * N_EMBD + col) = l0;
        *(uint32_t*)(yh + rowb * N_EMBD + col) = h1;
        *(uint32_t*)(yl + rowb * N_EMBD + col) = l1;
    }
}

// ---------------------------------------------------------------------------
// Launch
// ---------------------------------------------------------------------------
extern "C" void kernel_launch(void* const* d_in, const int* in_sizes, int n_in,
                              void* d_out, int out_size)
{
    const float* x      = (const float*)d_in[0];
    const float* w_attn = (const float*)d_in[1];
    const float* w_proj = (const float*)d_in[2];
    float* out = (float*)d_out;

    __half *Ah, *Al, *Wa, *Wp, *Qh, *Ql, *Kb, *Vh, *Vt;
    cudaGetSymbolAddress((void**)&Ah, g_Ah);
    cudaGetSymbolAddress((void**)&Al, g_Al);
    cudaGetSymbolAddress((void**)&Wa, g_Wa);
    cudaGetSymbolAddress((void**)&Wp, g_Wp);
    cudaGetSymbolAddress((void**)&Qh, g_Qh);
    cudaGetSymbolAddress((void**)&Ql, g_Ql);
    cudaGetSymbolAddress((void**)&Kb, g_K);
    cudaGetSymbolAddress((void**)&Vh, g_Vh);
    cudaGetSymbolAddress((void**)&Vt, g_Vt);

    cudaFuncSetAttribute(gemm_qkv_kernel,
                         cudaFuncAttributeMaxDynamicSharedMemorySize, GEMM_SMEM);
    cudaFuncSetAttribute(gemm_mma_kernel,
                         cudaFuncAttributeMaxDynamicSharedMemorySize, GEMM_SMEM);
    cudaFuncSetAttribute(flash_mma_kernel,
                         cudaFuncAttributeMaxDynamicSharedMemorySize, FA_SMEM);

    const int n4 = MROWS * N_EMBD / 4;

    // 1. RoPE table
    rope_table_kernel<<<(TT * 64 + 255) / 256, 256>>>();

    // 2. Convert x (split hi/lo) and both weights (transposed single fp16)
    conv_rm_kernel<<<(n4 + 255) / 256, 256>>>(x, Ah, Al, n4);
    conv_tr_kernel<<<dim3(QKV_N / 32, N_EMBD / 32), dim3(32, 8)>>>(
        w_attn, Wa, N_EMBD, QKV_N);
    conv_tr_kernel<<<dim3(N_EMBD / 32, N_EMBD / 32), dim3(32, 8)>>>(
        w_proj, Wp, N_EMBD, N_EMBD);

    // 3. QKV projection with fused RoPE + fp16 conversion epilogue
    gemm_qkv_kernel<<<dim3(QKV_N / BN, MROWS / BM), 256, GEMM_SMEM>>>(
        Ah, Al, Wa, Qh, Ql, Kb, Vh);

    // 4. V transpose (fp16 -> fp16 per-head)
    conv_vth_kernel<<<dim3(TT / 32, HD / 32, BB * NH), dim3(32, 8)>>>(Vh, Vt);

    // 5. Flash attention -> split fp16 O directly into Ah/Al
    flash_mma_kernel<<<dim3(TT / 128, NH, BB), 256, FA_SMEM>>>(
        Qh, Ql, Kb, Vt, Ah, Al);

    // 6. Output projection (fp32 out)
    gemm_mma_kernel<<<dim3(N_EMBD / BN, MROWS / BM), 256, GEMM_SMEM>>>(
        Ah, Al, Wp, out, MROWS, N_EMBD, N_EMBD);
}